// round 2
// baseline (speedup 1.0000x reference)
#include <cuda_runtime.h>
#include <math.h>

// Problem constants
#define SEQ 1024
#define DIM 128
#define NBM 8      // B*M
#define NHEAD 8    // heads per (b,m)
#define NG 64      // total heads = NBM*NHEAD

// Scratch (static device globals; no dynamic allocation allowed)
__device__ float g_qh[(size_t)NG * SEQ * DIM];
__device__ float g_kh[(size_t)NG * SEQ * DIM];
__device__ float g_vh[(size_t)NG * SEQ * DIM];
__device__ float g_oh[(size_t)NG * SEQ * DIM];

// ---------------------------------------------------------------------------
// Kernel 1: projections.  For each (mat in {q,k,v}, bm in 0..7):
//   Y[s, e] = sum_c X[bm, s, c] * W[m, c, e],  e = h*128 + d
// stored head-split:  g_Xh[((bm*8 + h)*1024 + s)*128 + d]
// Classic 128x128 tile SGEMM, BK=8, 256 threads, 8x8 per-thread microtile.
// blockIdx.x = head (BN=128 == D so one head per col-tile), .y = s-tile, .z = 24 gemms
// ---------------------------------------------------------------------------
__global__ void __launch_bounds__(256, 2) proj_kernel(
    const float* __restrict__ q, const float* __restrict__ k, const float* __restrict__ v,
    const float* __restrict__ Wq, const float* __restrict__ Wk, const float* __restrict__ Wv)
{
    __shared__ float As[8][132];   // [k][row], padded
    __shared__ float Bs[8][128];   // [k][col]

    const int z   = blockIdx.z;
    const int mat = z >> 3;
    const int bm  = z & 7;
    const int m   = bm & 3;

    const float* X = (mat == 0 ? q : mat == 1 ? k : v) + (size_t)bm * SEQ * DIM;
    const float* W = (mat == 0 ? Wq : mat == 1 ? Wk : Wv) + (size_t)m * DIM * (NHEAD * DIM);
    float*       Y = (mat == 0 ? g_qh : mat == 1 ? g_kh : g_vh) + (size_t)bm * NHEAD * SEQ * DIM;

    const int tid = threadIdx.x;
    const int ty  = tid >> 4;        // 0..15
    const int tx  = tid & 15;        // 0..15
    const int bx  = blockIdx.x;      // head 0..7
    const int by  = blockIdx.y;      // s-tile 0..7

    const int arow = tid >> 1;             // 0..127
    const int ak   = (tid & 1) * 4;        // 0 or 4
    const int brow = tid >> 5;             // 0..7
    const int bc   = (tid & 31) * 4;       // 0..124

    float acc[8][8];
#pragma unroll
    for (int i = 0; i < 8; i++)
#pragma unroll
        for (int j = 0; j < 8; j++) acc[i][j] = 0.f;

    for (int k0 = 0; k0 < DIM; k0 += 8) {
        float4 av = *(const float4*)(X + (size_t)(by * 128 + arow) * DIM + k0 + ak);
        float4 bv = *(const float4*)(W + (size_t)(k0 + brow) * (NHEAD * DIM) + bx * 128 + bc);
        __syncthreads();
        As[ak + 0][arow] = av.x;
        As[ak + 1][arow] = av.y;
        As[ak + 2][arow] = av.z;
        As[ak + 3][arow] = av.w;
        *(float4*)&Bs[brow][bc] = bv;
        __syncthreads();
#pragma unroll
        for (int kk = 0; kk < 8; kk++) {
            float4 a0 = *(const float4*)&As[kk][ty * 8];
            float4 a1 = *(const float4*)&As[kk][ty * 8 + 4];
            float4 b0 = *(const float4*)&Bs[kk][tx * 8];
            float4 b1 = *(const float4*)&Bs[kk][tx * 8 + 4];
            float a[8] = {a0.x, a0.y, a0.z, a0.w, a1.x, a1.y, a1.z, a1.w};
            float b[8] = {b0.x, b0.y, b0.z, b0.w, b1.x, b1.y, b1.z, b1.w};
#pragma unroll
            for (int i = 0; i < 8; i++)
#pragma unroll
                for (int j = 0; j < 8; j++)
                    acc[i][j] = fmaf(a[i], b[j], acc[i][j]);
        }
    }

#pragma unroll
    for (int i = 0; i < 8; i++) {
        int s = by * 128 + ty * 8 + i;
        float* dst = Y + ((size_t)bx * SEQ + s) * DIM + tx * 8;
        *(float4*)(dst)     = make_float4(acc[i][0], acc[i][1], acc[i][2], acc[i][3]);
        *(float4*)(dst + 4) = make_float4(acc[i][4], acc[i][5], acc[i][6], acc[i][7]);
    }
}

// ---------------------------------------------------------------------------
// Kernel 2: flash attention per head, fp32, online softmax.
// Block = (head g, q-tile of 64 rows), 512 threads (16 warps).
// Q kept in smem transposed (d-major) so QK^T fragment loads are conflict-free;
// K/V row-major; P staged in smem between S-phase and PV-phase.
// grid = (16, 64)
// ---------------------------------------------------------------------------
#define QTS_STRIDE 66
#define PS_STRIDE  68
#define QTS_F (DIM * QTS_STRIDE)          // 8448
#define KS_F  (64 * DIM)                  // 8192
#define VS_F  (64 * DIM)                  // 8192
#define PS_F  (64 * PS_STRIDE)            // 4352
#define ATTN_SMEM_BYTES ((QTS_F + KS_F + VS_F + PS_F + 192) * 4)   // 117504

__global__ void __launch_bounds__(512, 1) attn_kernel()
{
    extern __shared__ float smf[];
    float* qts  = smf;                 // [d][r] transposed, stride 66
    float* ks   = qts + QTS_F;         // [c][d]
    float* vs   = ks + KS_F;           // [c][d]
    float* ps   = vs + VS_F;           // [r][c], stride 68
    float* rowm = ps + PS_F;
    float* rowl = rowm + 64;
    float* rowc = rowl + 64;

    const int g    = blockIdx.y;       // head 0..63
    const int qt   = blockIdx.x;       // 0..15
    const int tid  = threadIdx.x;
    const int warp = tid >> 5;
    const int lane = tid & 31;

    const float scale = 0.08838834764831845f;   // 1/sqrt(128)

    const float* Qg = g_qh + ((size_t)g * SEQ + qt * 64) * DIM;
    const float* Kg = g_kh + (size_t)g * SEQ * DIM;
    const float* Vg = g_vh + (size_t)g * SEQ * DIM;

    // Load Q tile transposed (pre-scaled)
#pragma unroll
    for (int it = 0; it < 4; it++) {
        int idx = tid + it * 512;
        int r   = idx >> 5;
        int d4  = (idx & 31) * 4;
        float4 qv = *(const float4*)(Qg + (size_t)r * DIM + d4);
        qts[(d4 + 0) * QTS_STRIDE + r] = qv.x * scale;
        qts[(d4 + 1) * QTS_STRIDE + r] = qv.y * scale;
        qts[(d4 + 2) * QTS_STRIDE + r] = qv.z * scale;
        qts[(d4 + 3) * QTS_STRIDE + r] = qv.w * scale;
    }
    if (tid < 64) { rowm[tid] = -1e30f; rowl[tid] = 0.f; }

    float o[4][4];
#pragma unroll
    for (int i = 0; i < 4; i++)
#pragma unroll
        for (int j = 0; j < 4; j++) o[i][j] = 0.f;

    const int sr0 = lane * 2;   // S rows owned in S-phase
    const int sc0 = warp * 4;   // S cols owned in S-phase
    const int pr0 = warp * 4;   // O rows owned in PV-phase
    const int pd  = lane * 4;   // O cols owned in PV-phase

    for (int t = 0; t < 16; t++) {
        __syncthreads();   // prior PV done with vs/ps
        // Load K/V tile (coalesced)
#pragma unroll
        for (int it = 0; it < 4; it++) {
            int idx = tid + it * 512;
            int r   = idx >> 5;
            int d4  = (idx & 31) * 4;
            *(float4*)(ks + r * DIM + d4) = *(const float4*)(Kg + (size_t)(t * 64 + r) * DIM + d4);
            *(float4*)(vs + r * DIM + d4) = *(const float4*)(Vg + (size_t)(t * 64 + r) * DIM + d4);
        }
        __syncthreads();

        // ---- S = (Q*scale) K^T : each thread 2 rows x 4 cols ----
        float acc[2][4];
#pragma unroll
        for (int i = 0; i < 2; i++)
#pragma unroll
            for (int j = 0; j < 4; j++) acc[i][j] = 0.f;

#pragma unroll 8
        for (int d = 0; d < DIM; d += 4) {
            float4 kf[4];
#pragma unroll
            for (int j = 0; j < 4; j++)
                kf[j] = *(const float4*)(ks + (sc0 + j) * DIM + d);   // warp-uniform (broadcast)
#pragma unroll
            for (int dd = 0; dd < 4; dd++) {
                float2 q2 = *(const float2*)(qts + (d + dd) * QTS_STRIDE + sr0);
#pragma unroll
                for (int j = 0; j < 4; j++) {
                    float kv = ((const float*)&kf[j])[dd];
                    acc[0][j] = fmaf(q2.x, kv, acc[0][j]);
                    acc[1][j] = fmaf(q2.y, kv, acc[1][j]);
                }
            }
        }
#pragma unroll
        for (int i = 0; i < 2; i++)
#pragma unroll
            for (int j = 0; j < 4; j++)
                ps[(sr0 + i) * PS_STRIDE + sc0 + j] = acc[i][j];
        __syncthreads();

        // ---- online softmax stats: 8 threads per row ----
        {
            int rr  = tid >> 3;
            int sub = tid & 7;
            float* prow = ps + rr * PS_STRIDE + sub * 8;
            float m_old = rowm[rr];
            float mx = -1e30f;
#pragma unroll
            for (int j = 0; j < 8; j++) mx = fmaxf(mx, prow[j]);
#pragma unroll
            for (int off = 4; off > 0; off >>= 1)
                mx = fmaxf(mx, __shfl_xor_sync(0xffffffffu, mx, off));
            float m_new = fmaxf(m_old, mx);
            float corr  = __expf(m_old - m_new);
            float sum = 0.f;
#pragma unroll
            for (int j = 0; j < 8; j++) {
                float p = __expf(prow[j] - m_new);
                prow[j] = p;
                sum += p;
            }
#pragma unroll
            for (int off = 4; off > 0; off >>= 1)
                sum += __shfl_xor_sync(0xffffffffu, sum, off);
            if (sub == 0) {
                rowm[rr] = m_new;
                rowl[rr] = rowl[rr] * corr + sum;
                rowc[rr] = corr;
            }
        }
        __syncthreads();

        // ---- O = O*corr + P @ V : each thread 4 rows x 4 cols ----
        {
#pragma unroll
            for (int i = 0; i < 4; i++) {
                float cr = rowc[pr0 + i];
#pragma unroll
                for (int j = 0; j < 4; j++) o[i][j] *= cr;
            }
#pragma unroll
            for (int c = 0; c < 64; c += 4) {
                float4 pf[4];
#pragma unroll
                for (int i = 0; i < 4; i++)
                    pf[i] = *(const float4*)(ps + (pr0 + i) * PS_STRIDE + c);  // warp-uniform
#pragma unroll
                for (int cc = 0; cc < 4; cc++) {
                    float4 vv = *(const float4*)(vs + (c + cc) * DIM + pd);
#pragma unroll
                    for (int i = 0; i < 4; i++) {
                        float pw = ((const float*)&pf[i])[cc];
                        o[i][0] = fmaf(pw, vv.x, o[i][0]);
                        o[i][1] = fmaf(pw, vv.y, o[i][1]);
                        o[i][2] = fmaf(pw, vv.z, o[i][2]);
                        o[i][3] = fmaf(pw, vv.w, o[i][3]);
                    }
                }
            }
        }
    }

    // Epilogue: normalize and store per-head output
    float* Og = g_oh + ((size_t)g * SEQ + qt * 64) * DIM;
#pragma unroll
    for (int i = 0; i < 4; i++) {
        float inv = 1.0f / rowl[pr0 + i];
        *(float4*)(Og + (size_t)(pr0 + i) * DIM + pd) =
            make_float4(o[i][0] * inv, o[i][1] * inv, o[i][2] * inv, o[i][3] * inv);
    }
}

// ---------------------------------------------------------------------------
// Kernel 3: mean over heads + residual.  out[bm,s,d] = q[bm,s,d] + mean_h oh
// One float4 per thread: 262144 threads.
// ---------------------------------------------------------------------------
__global__ void __launch_bounds__(256) reduce_kernel(const float* __restrict__ q,
                                                     float* __restrict__ out)
{
    int i4 = blockIdx.x * 256 + threadIdx.x;    // 0..262143
    int bm = i4 >> 15;                           // / 32768 float4 per (b,m)
    int r4 = i4 & 32767;
    const float4* oh4 = (const float4*)g_oh;
    float sx = 0.f, sy = 0.f, sz = 0.f, sw = 0.f;
#pragma unroll
    for (int h = 0; h < NHEAD; h++) {
        float4 t = oh4[(size_t)(bm * NHEAD + h) * 32768 + r4];
        sx += t.x; sy += t.y; sz += t.z; sw += t.w;
    }
    float4 qv = ((const float4*)q)[i4];
    ((float4*)out)[i4] = make_float4(qv.x + 0.125f * sx, qv.y + 0.125f * sy,
                                     qv.z + 0.125f * sz, qv.w + 0.125f * sw);
}

// ---------------------------------------------------------------------------
extern "C" void kernel_launch(void* const* d_in, const int* in_sizes, int n_in,
                              void* d_out, int out_size)
{
    const float* q  = (const float*)d_in[0];
    const float* k  = (const float*)d_in[1];
    const float* v  = (const float*)d_in[2];
    const float* Wq = (const float*)d_in[3];
    const float* Wk = (const float*)d_in[4];
    const float* Wv = (const float*)d_in[5];
    float* out = (float*)d_out;

    cudaFuncSetAttribute(attn_kernel, cudaFuncAttributeMaxDynamicSharedMemorySize,
                         ATTN_SMEM_BYTES);

    proj_kernel<<<dim3(8, 8, 24), 256>>>(q, k, v, Wq, Wk, Wv);
    attn_kernel<<<dim3(16, 64), 512, ATTN_SMEM_BYTES>>>();
    reduce_kernel<<<1024, 256>>>(q, out);
}

// round 3
// speedup vs baseline: 1.0014x; 1.0014x over previous
#include <cuda_runtime.h>
#include <math.h>

// Problem constants
#define SEQ 1024
#define DIM 128
#define NBM 8      // B*M
#define NHEAD 8    // heads per (b,m)
#define NG 64      // total heads = NBM*NHEAD

// Scratch (static device globals; no dynamic allocation allowed)
__device__ float g_qh[(size_t)NG * SEQ * DIM];
__device__ float g_kh[(size_t)NG * SEQ * DIM];
__device__ float g_vh[(size_t)NG * SEQ * DIM];
__device__ float g_oh[(size_t)NG * SEQ * DIM];

// ---------------------------------------------------------------------------
// Kernel 1: projections.  For each (mat in {q,k,v}, bm in 0..7):
//   Y[s, e] = sum_c X[bm, s, c] * W[m, c, e],  e = h*128 + d
// stored head-split:  g_Xh[((bm*8 + h)*1024 + s)*128 + d]
// Classic 128x128 tile SGEMM, BK=8, 256 threads, 8x8 per-thread microtile.
// blockIdx.x = head (BN=128 == D so one head per col-tile), .y = s-tile, .z = 24 gemms
// ---------------------------------------------------------------------------
__global__ void __launch_bounds__(256, 2) proj_kernel(
    const float* __restrict__ q, const float* __restrict__ k, const float* __restrict__ v,
    const float* __restrict__ Wq, const float* __restrict__ Wk, const float* __restrict__ Wv)
{
    __shared__ float As[8][132];   // [k][row], padded
    __shared__ float Bs[8][128];   // [k][col]

    const int z   = blockIdx.z;
    const int mat = z >> 3;
    const int bm  = z & 7;
    const int m   = bm & 3;

    const float* X = (mat == 0 ? q : mat == 1 ? k : v) + (size_t)bm * SEQ * DIM;
    const float* W = (mat == 0 ? Wq : mat == 1 ? Wk : Wv) + (size_t)m * DIM * (NHEAD * DIM);
    float*       Y = (mat == 0 ? g_qh : mat == 1 ? g_kh : g_vh) + (size_t)bm * NHEAD * SEQ * DIM;

    const int tid = threadIdx.x;
    const int ty  = tid >> 4;        // 0..15
    const int tx  = tid & 15;        // 0..15
    const int bx  = blockIdx.x;      // head 0..7
    const int by  = blockIdx.y;      // s-tile 0..7

    const int arow = tid >> 1;             // 0..127
    const int ak   = (tid & 1) * 4;        // 0 or 4
    const int brow = tid >> 5;             // 0..7
    const int bc   = (tid & 31) * 4;       // 0..124

    float acc[8][8];
#pragma unroll
    for (int i = 0; i < 8; i++)
#pragma unroll
        for (int j = 0; j < 8; j++) acc[i][j] = 0.f;

    for (int k0 = 0; k0 < DIM; k0 += 8) {
        float4 av = *(const float4*)(X + (size_t)(by * 128 + arow) * DIM + k0 + ak);
        float4 bv = *(const float4*)(W + (size_t)(k0 + brow) * (NHEAD * DIM) + bx * 128 + bc);
        __syncthreads();
        As[ak + 0][arow] = av.x;
        As[ak + 1][arow] = av.y;
        As[ak + 2][arow] = av.z;
        As[ak + 3][arow] = av.w;
        *(float4*)&Bs[brow][bc] = bv;
        __syncthreads();
#pragma unroll
        for (int kk = 0; kk < 8; kk++) {
            float4 a0 = *(const float4*)&As[kk][ty * 8];
            float4 a1 = *(const float4*)&As[kk][ty * 8 + 4];
            float4 b0 = *(const float4*)&Bs[kk][tx * 8];
            float4 b1 = *(const float4*)&Bs[kk][tx * 8 + 4];
            float a[8] = {a0.x, a0.y, a0.z, a0.w, a1.x, a1.y, a1.z, a1.w};
            float b[8] = {b0.x, b0.y, b0.z, b0.w, b1.x, b1.y, b1.z, b1.w};
#pragma unroll
            for (int i = 0; i < 8; i++)
#pragma unroll
                for (int j = 0; j < 8; j++)
                    acc[i][j] = fmaf(a[i], b[j], acc[i][j]);
        }
    }

#pragma unroll
    for (int i = 0; i < 8; i++) {
        int s = by * 128 + ty * 8 + i;
        float* dst = Y + ((size_t)bx * SEQ + s) * DIM + tx * 8;
        *(float4*)(dst)     = make_float4(acc[i][0], acc[i][1], acc[i][2], acc[i][3]);
        *(float4*)(dst + 4) = make_float4(acc[i][4], acc[i][5], acc[i][6], acc[i][7]);
    }
}

// ---------------------------------------------------------------------------
// Kernel 2: flash attention per head, fp32, online softmax.
// Block = (head g, q-tile of 64 rows), 512 threads (16 warps).
// Q kept in smem transposed (d-major) so QK^T fragment loads are conflict-free;
// K/V row-major; P staged in smem between S-phase and PV-phase.
// grid = (16, 64)
// ---------------------------------------------------------------------------
#define QTS_STRIDE 66
#define PS_STRIDE  68
#define QTS_F (DIM * QTS_STRIDE)          // 8448
#define KS_F  (64 * DIM)                  // 8192
#define VS_F  (64 * DIM)                  // 8192
#define PS_F  (64 * PS_STRIDE)            // 4352
#define ATTN_SMEM_BYTES ((QTS_F + KS_F + VS_F + PS_F + 192) * 4)   // 117504

__global__ void __launch_bounds__(512, 1) attn_kernel()
{
    extern __shared__ float smf[];
    float* qts  = smf;                 // [d][r] transposed, stride 66
    float* ks   = qts + QTS_F;         // [c][d]
    float* vs   = ks + KS_F;           // [c][d]
    float* ps   = vs + VS_F;           // [r][c], stride 68
    float* rowm = ps + PS_F;
    float* rowl = rowm + 64;
    float* rowc = rowl + 64;

    const int g    = blockIdx.y;       // head 0..63
    const int qt   = blockIdx.x;       // 0..15
    const int tid  = threadIdx.x;
    const int warp = tid >> 5;
    const int lane = tid & 31;

    const float scale = 0.08838834764831845f;   // 1/sqrt(128)

    const float* Qg = g_qh + ((size_t)g * SEQ + qt * 64) * DIM;
    const float* Kg = g_kh + (size_t)g * SEQ * DIM;
    const float* Vg = g_vh + (size_t)g * SEQ * DIM;

    // Load Q tile transposed (pre-scaled)
#pragma unroll
    for (int it = 0; it < 4; it++) {
        int idx = tid + it * 512;
        int r   = idx >> 5;
        int d4  = (idx & 31) * 4;
        float4 qv = *(const float4*)(Qg + (size_t)r * DIM + d4);
        qts[(d4 + 0) * QTS_STRIDE + r] = qv.x * scale;
        qts[(d4 + 1) * QTS_STRIDE + r] = qv.y * scale;
        qts[(d4 + 2) * QTS_STRIDE + r] = qv.z * scale;
        qts[(d4 + 3) * QTS_STRIDE + r] = qv.w * scale;
    }
    if (tid < 64) { rowm[tid] = -1e30f; rowl[tid] = 0.f; }

    float o[4][4];
#pragma unroll
    for (int i = 0; i < 4; i++)
#pragma unroll
        for (int j = 0; j < 4; j++) o[i][j] = 0.f;

    const int sr0 = lane * 2;   // S rows owned in S-phase
    const int sc0 = warp * 4;   // S cols owned in S-phase
    const int pr0 = warp * 4;   // O rows owned in PV-phase
    const int pd  = lane * 4;   // O cols owned in PV-phase

    for (int t = 0; t < 16; t++) {
        __syncthreads();   // prior PV done with vs/ps
        // Load K/V tile (coalesced)
#pragma unroll
        for (int it = 0; it < 4; it++) {
            int idx = tid + it * 512;
            int r   = idx >> 5;
            int d4  = (idx & 31) * 4;
            *(float4*)(ks + r * DIM + d4) = *(const float4*)(Kg + (size_t)(t * 64 + r) * DIM + d4);
            *(float4*)(vs + r * DIM + d4) = *(const float4*)(Vg + (size_t)(t * 64 + r) * DIM + d4);
        }
        __syncthreads();

        // ---- S = (Q*scale) K^T : each thread 2 rows x 4 cols ----
        float acc[2][4];
#pragma unroll
        for (int i = 0; i < 2; i++)
#pragma unroll
            for (int j = 0; j < 4; j++) acc[i][j] = 0.f;

#pragma unroll 8
        for (int d = 0; d < DIM; d += 4) {
            float4 kf[4];
#pragma unroll
            for (int j = 0; j < 4; j++)
                kf[j] = *(const float4*)(ks + (sc0 + j) * DIM + d);   // warp-uniform (broadcast)
#pragma unroll
            for (int dd = 0; dd < 4; dd++) {
                float2 q2 = *(const float2*)(qts + (d + dd) * QTS_STRIDE + sr0);
#pragma unroll
                for (int j = 0; j < 4; j++) {
                    float kv = ((const float*)&kf[j])[dd];
                    acc[0][j] = fmaf(q2.x, kv, acc[0][j]);
                    acc[1][j] = fmaf(q2.y, kv, acc[1][j]);
                }
            }
        }
#pragma unroll
        for (int i = 0; i < 2; i++)
#pragma unroll
            for (int j = 0; j < 4; j++)
                ps[(sr0 + i) * PS_STRIDE + sc0 + j] = acc[i][j];
        __syncthreads();

        // ---- online softmax stats: 8 threads per row ----
        {
            int rr  = tid >> 3;
            int sub = tid & 7;
            float* prow = ps + rr * PS_STRIDE + sub * 8;
            float m_old = rowm[rr];
            float mx = -1e30f;
#pragma unroll
            for (int j = 0; j < 8; j++) mx = fmaxf(mx, prow[j]);
#pragma unroll
            for (int off = 4; off > 0; off >>= 1)
                mx = fmaxf(mx, __shfl_xor_sync(0xffffffffu, mx, off));
            float m_new = fmaxf(m_old, mx);
            float corr  = __expf(m_old - m_new);
            float sum = 0.f;
#pragma unroll
            for (int j = 0; j < 8; j++) {
                float p = __expf(prow[j] - m_new);
                prow[j] = p;
                sum += p;
            }
#pragma unroll
            for (int off = 4; off > 0; off >>= 1)
                sum += __shfl_xor_sync(0xffffffffu, sum, off);
            if (sub == 0) {
                rowm[rr] = m_new;
                rowl[rr] = rowl[rr] * corr + sum;
                rowc[rr] = corr;
            }
        }
        __syncthreads();

        // ---- O = O*corr + P @ V : each thread 4 rows x 4 cols ----
        {
#pragma unroll
            for (int i = 0; i < 4; i++) {
                float cr = rowc[pr0 + i];
#pragma unroll
                for (int j = 0; j < 4; j++) o[i][j] *= cr;
            }
#pragma unroll
            for (int c = 0; c < 64; c += 4) {
                float4 pf[4];
#pragma unroll
                for (int i = 0; i < 4; i++)
                    pf[i] = *(const float4*)(ps + (pr0 + i) * PS_STRIDE + c);  // warp-uniform
#pragma unroll
                for (int cc = 0; cc < 4; cc++) {
                    float4 vv = *(const float4*)(vs + (c + cc) * DIM + pd);
#pragma unroll
                    for (int i = 0; i < 4; i++) {
                        float pw = ((const float*)&pf[i])[cc];
                        o[i][0] = fmaf(pw, vv.x, o[i][0]);
                        o[i][1] = fmaf(pw, vv.y, o[i][1]);
                        o[i][2] = fmaf(pw, vv.z, o[i][2]);
                        o[i][3] = fmaf(pw, vv.w, o[i][3]);
                    }
                }
            }
        }
    }

    // Epilogue: normalize and store per-head output
    float* Og = g_oh + ((size_t)g * SEQ + qt * 64) * DIM;
#pragma unroll
    for (int i = 0; i < 4; i++) {
        float inv = 1.0f / rowl[pr0 + i];
        *(float4*)(Og + (size_t)(pr0 + i) * DIM + pd) =
            make_float4(o[i][0] * inv, o[i][1] * inv, o[i][2] * inv, o[i][3] * inv);
    }
}

// ---------------------------------------------------------------------------
// Kernel 3: mean over heads + residual.  out[bm,s,d] = q[bm,s,d] + mean_h oh
// One float4 per thread: 262144 threads.
// ---------------------------------------------------------------------------
__global__ void __launch_bounds__(256) reduce_kernel(const float* __restrict__ q,
                                                     float* __restrict__ out)
{
    int i4 = blockIdx.x * 256 + threadIdx.x;    // 0..262143
    int bm = i4 >> 15;                           // / 32768 float4 per (b,m)
    int r4 = i4 & 32767;
    const float4* oh4 = (const float4*)g_oh;
    float sx = 0.f, sy = 0.f, sz = 0.f, sw = 0.f;
#pragma unroll
    for (int h = 0; h < NHEAD; h++) {
        float4 t = oh4[(size_t)(bm * NHEAD + h) * 32768 + r4];
        sx += t.x; sy += t.y; sz += t.z; sw += t.w;
    }
    float4 qv = ((const float4*)q)[i4];
    ((float4*)out)[i4] = make_float4(qv.x + 0.125f * sx, qv.y + 0.125f * sy,
                                     qv.z + 0.125f * sz, qv.w + 0.125f * sw);
}

// ---------------------------------------------------------------------------
extern "C" void kernel_launch(void* const* d_in, const int* in_sizes, int n_in,
                              void* d_out, int out_size)
{
    const float* q  = (const float*)d_in[0];
    const float* k  = (const float*)d_in[1];
    const float* v  = (const float*)d_in[2];
    const float* Wq = (const float*)d_in[3];
    const float* Wk = (const float*)d_in[4];
    const float* Wv = (const float*)d_in[5];
    float* out = (float*)d_out;

    cudaFuncSetAttribute(attn_kernel, cudaFuncAttributeMaxDynamicSharedMemorySize,
                         ATTN_SMEM_BYTES);

    proj_kernel<<<dim3(8, 8, 24), 256>>>(q, k, v, Wq, Wk, Wv);
    attn_kernel<<<dim3(16, 64), 512, ATTN_SMEM_BYTES>>>();
    reduce_kernel<<<1024, 256>>>(q, out);
}

// round 5
// speedup vs baseline: 2.7584x; 2.7546x over previous
#include <cuda_runtime.h>
#include <cuda_fp16.h>
#include <cstdint>

#define SEQ 1024
#define DIM 128
#define NG 64

// fp16 hi/lo split operands, produced by proj epilogue
__device__ __half g_qh0[(size_t)NG*SEQ*DIM];
__device__ __half g_qh1[(size_t)NG*SEQ*DIM];
__device__ __half g_kh0[(size_t)NG*SEQ*DIM];
__device__ __half g_kh1[(size_t)NG*SEQ*DIM];
__device__ __half g_vh0[(size_t)NG*SEQ*DIM];
__device__ __half g_vh1[(size_t)NG*SEQ*DIM];
__device__ float  g_oh [(size_t)NG*SEQ*DIM];

// ---------------- helpers ----------------
__device__ __forceinline__ uint32_t s2u(const void* p){
    uint32_t a; asm("{ .reg .u64 t; cvta.to.shared.u64 t,%1; cvt.u32.u64 %0,t; }":"=r"(a):"l"(p)); return a;
}
__device__ __forceinline__ void cpa16(uint32_t d, const void* s){
    asm volatile("cp.async.cg.shared.global [%0],[%1],16;"::"r"(d),"l"(s));
}
#define CPCOMMIT() asm volatile("cp.async.commit_group;":::"memory")
#define CPWAIT1()  asm volatile("cp.async.wait_group 1;":::"memory")
#define CPWAIT0()  asm volatile("cp.async.wait_group 0;":::"memory")

__device__ __forceinline__ void ldm4(uint32_t r[4], uint32_t a){
    asm volatile("ldmatrix.sync.aligned.m8n8.x4.shared.b16 {%0,%1,%2,%3},[%4];"
        :"=r"(r[0]),"=r"(r[1]),"=r"(r[2]),"=r"(r[3]):"r"(a));
}
__device__ __forceinline__ void ldm4t(uint32_t r[4], uint32_t a){
    asm volatile("ldmatrix.sync.aligned.m8n8.x4.trans.shared.b16 {%0,%1,%2,%3},[%4];"
        :"=r"(r[0]),"=r"(r[1]),"=r"(r[2]),"=r"(r[3]):"r"(a));
}
__device__ __forceinline__ void mmaf(float c[4], const uint32_t a[4], uint32_t b0, uint32_t b1){
    asm volatile("mma.sync.aligned.m16n8k16.row.col.f32.f16.f16.f32 "
        "{%0,%1,%2,%3},{%4,%5,%6,%7},{%8,%9},{%0,%1,%2,%3};"
        :"+f"(c[0]),"+f"(c[1]),"+f"(c[2]),"+f"(c[3])
        :"r"(a[0]),"r"(a[1]),"r"(a[2]),"r"(a[3]),"r"(b0),"r"(b1));
}
__device__ __forceinline__ uint32_t pkh(float a, float b){
    __half2 h = __floats2half2_rn(a,b); return *(uint32_t*)&h;
}
// fast 2^x, x <= 0, FMA-pipe only (5th-order poly)
__device__ __forceinline__ float fex2(float x){
    x = fmaxf(x, -120.f);
    float xf = floorf(x), f = x - xf;
    float p = fmaf(f, 0.0013333558f, 0.0096181291f);
    p = fmaf(f, p, 0.0555041087f);
    p = fmaf(f, p, 0.2402265070f);
    p = fmaf(f, p, 0.6931471806f);
    p = fmaf(f, p, 1.0f);
    return __int_as_float(((int)xf + 127) << 23) * p;
}
// swizzled half-index into a [rows][128] fp16 smem tile (conflict-free ldmatrix)
#define SWZH(r,d) ((r)*128 + ((((d)>>3)^((r)&7))<<3) + ((d)&7))

// smem map (half indices): Qh 0, Ql 16384; K/V buffers at 32768, stride 32768
#define SM_KV 32768
#define ATTN_SMEM (196608)

// ---------------- Kernel 1: projections (fp32 sgemm, fp16-split epilogue) ----
__global__ void __launch_bounds__(256,2) proj_kernel(
    const float* __restrict__ q, const float* __restrict__ k, const float* __restrict__ v,
    const float* __restrict__ Wq, const float* __restrict__ Wk, const float* __restrict__ Wv)
{
    __shared__ float As[8][132], Bs[8][128];
    const int z=blockIdx.z, mat=z>>3, bm=z&7, m=bm&3;
    const float* X=(mat==0?q:mat==1?k:v)+(size_t)bm*SEQ*DIM;
    const float* W=(mat==0?Wq:mat==1?Wk:Wv)+(size_t)m*DIM*(8*DIM);
    const int tid=threadIdx.x, ty=tid>>4, tx=tid&15;
    const int bx=blockIdx.x, by=blockIdx.y;
    const int arow=tid>>1, ak=(tid&1)*4, brow=tid>>5, bc=(tid&31)*4;
    float acc[8][8];
#pragma unroll
    for(int i=0;i<8;i++)
#pragma unroll
        for(int j=0;j<8;j++) acc[i][j]=0.f;
    for(int k0=0;k0<DIM;k0+=8){
        float4 av=*(const float4*)(X+(size_t)(by*128+arow)*DIM+k0+ak);
        float4 bv=*(const float4*)(W+(size_t)(k0+brow)*(8*DIM)+bx*128+bc);
        __syncthreads();
        As[ak+0][arow]=av.x; As[ak+1][arow]=av.y; As[ak+2][arow]=av.z; As[ak+3][arow]=av.w;
        *(float4*)&Bs[brow][bc]=bv;
        __syncthreads();
#pragma unroll
        for(int kk=0;kk<8;kk++){
            float4 a0=*(const float4*)&As[kk][ty*8], a1=*(const float4*)&As[kk][ty*8+4];
            float4 b0=*(const float4*)&Bs[kk][tx*8], b1=*(const float4*)&Bs[kk][tx*8+4];
            float a[8]={a0.x,a0.y,a0.z,a0.w,a1.x,a1.y,a1.z,a1.w};
            float b[8]={b0.x,b0.y,b0.z,b0.w,b1.x,b1.y,b1.z,b1.w};
#pragma unroll
            for(int i=0;i<8;i++)
#pragma unroll
                for(int j=0;j<8;j++) acc[i][j]=fmaf(a[i],b[j],acc[i][j]);
        }
    }
    const int g=bm*8+bx;
    __half *d0, *d1; float sc;
    if(mat==0){ d0=g_qh0; d1=g_qh1; sc=0.12753102001968606f; }        // log2(e)/sqrt(128)
    else if(mat==1){ d0=g_kh0; d1=g_kh1; sc=1.f; }
    else { d0=g_vh0; d1=g_vh1; sc=1.f; }
#pragma unroll
    for(int i=0;i<8;i++){
        size_t base=((size_t)(g*SEQ)+by*128+ty*8+i)*DIM+tx*8;
        __align__(16) __half h8[8], l8[8];
#pragma unroll
        for(int j=0;j<8;j++){
            float x=acc[i][j]*sc;
            __half h=__float2half_rn(x);
            h8[j]=h; l8[j]=__float2half_rn(x-__half2float(h));
        }
        *(uint4*)(d0+base)=*(uint4*)h8;
        *(uint4*)(d1+base)=*(uint4*)l8;
    }
}

// ---------------- Kernel 2: flash attention on mma.sync fp16 splits ----------
__device__ __forceinline__ void load_kv(uint32_t sb, size_t gbase, int t, int buf, int tid){
#pragma unroll
    for(int i=0;i<16;i++){
        int idx=tid+i*256, arr=idx>>10, rem=idx&1023, row=rem>>4, ch=rem&15;
        const __half* src;
        if(arr==0) src=g_kh0; else if(arr==1) src=g_kh1; else if(arr==2) src=g_vh0; else src=g_vh1;
        src += gbase+(size_t)(t*64+row)*DIM+ch*8;
        uint32_t dst=sb+2*(SM_KV+buf*32768+arr*8192+SWZH(row,ch*8));
        cpa16(dst,src);
    }
}

__global__ void __launch_bounds__(256,1) attn_kernel()
{
    extern __shared__ __half sm[];
    const uint32_t sb=s2u(sm);
    const int tid=threadIdx.x, warp=tid>>5, lane=tid&31;
    const int g=blockIdx.y, qt=blockIdx.x;
    const size_t gbase=(size_t)g*SEQ*DIM;
    // ldmatrix lane address components (same formula serves A, B, B-trans)
    const int lr=(lane&7)+((lane>>3)&1)*8;
    const int ldd=((lane>>4)&1)*8;

    // load Q (both splits) into smem
#pragma unroll
    for(int i=0;i<16;i++){
        int idx=tid+i*256, arr=idx>>11, rem=idx&2047, row=rem>>4, ch=rem&15;
        const __half* src=(arr? g_qh1:g_qh0)+gbase+(size_t)(qt*128+row)*DIM+ch*8;
        cpa16(sb+2*((arr?16384:0)+SWZH(row,ch*8)), src);
    }
    load_kv(sb,gbase,0,0,tid); CPCOMMIT();   // group: Q + tile0
    load_kv(sb,gbase,1,1,tid); CPCOMMIT();   // group: tile1

    float o[16][4];
#pragma unroll
    for(int i=0;i<16;i++)
#pragma unroll
        for(int j2=0;j2<4;j2++) o[i][j2]=0.f;
    float mA=-1e30f, mB=-1e30f, lA=0.f, lB=0.f;

    for(int t=0;t<16;t++){
        if(t<15) CPWAIT1(); else CPWAIT0();
        __syncthreads();
        const uint32_t KHB=SM_KV+(t&1)*32768, KLB=KHB+8192, VHB=KHB+16384, VLB=KHB+24576;

        // ---- S = Qh·Kh + Qh·Kl + Ql·Kh  (16 rows/warp x 64 keys) ----
        float c[8][4];
#pragma unroll
        for(int j=0;j<8;j++)
#pragma unroll
            for(int i2=0;i2<4;i2++) c[j][i2]=0.f;
#pragma unroll
        for(int kc=0;kc<8;kc++){
            uint32_t ah[4],al[4];
            ldm4(ah, sb+2*(SWZH(warp*16+lr, kc*16+ldd)));
            ldm4(al, sb+2*(16384+SWZH(warp*16+lr, kc*16+ldd)));
#pragma unroll
            for(int np=0;np<4;np++){
                uint32_t kh[4],kl[4];
                ldm4(kh, sb+2*(KHB+SWZH(np*16+lr, kc*16+ldd)));
                ldm4(kl, sb+2*(KLB+SWZH(np*16+lr, kc*16+ldd)));
                mmaf(c[2*np],ah,kh[0],kh[2]); mmaf(c[2*np+1],ah,kh[1],kh[3]);
                mmaf(c[2*np],ah,kl[0],kl[2]); mmaf(c[2*np+1],ah,kl[1],kl[3]);
                mmaf(c[2*np],al,kh[0],kh[2]); mmaf(c[2*np+1],al,kh[1],kh[3]);
            }
        }

        // ---- online softmax (rowA = lane>>2, rowB = +8) ----
        float tA=-1e30f, tB=-1e30f;
#pragma unroll
        for(int j=0;j<8;j++){
            tA=fmaxf(tA,fmaxf(c[j][0],c[j][1]));
            tB=fmaxf(tB,fmaxf(c[j][2],c[j][3]));
        }
        tA=fmaxf(tA,__shfl_xor_sync(0xffffffffu,tA,1));
        tA=fmaxf(tA,__shfl_xor_sync(0xffffffffu,tA,2));
        tB=fmaxf(tB,__shfl_xor_sync(0xffffffffu,tB,1));
        tB=fmaxf(tB,__shfl_xor_sync(0xffffffffu,tB,2));
        float mnA=fmaxf(mA,tA), mnB=fmaxf(mB,tB);
        float cA=fex2(mA-mnA), cB=fex2(mB-mnB);
        mA=mnA; mB=mnB;
        uint32_t pa[8], pb[8];
        float sA=0.f, sB=0.f;
#pragma unroll
        for(int j=0;j<8;j++){
            float p0=fex2(c[j][0]-mnA), p1=fex2(c[j][1]-mnA);
            float p2=fex2(c[j][2]-mnB), p3=fex2(c[j][3]-mnB);
            sA+=p0+p1; sB+=p2+p3;
            pa[j]=pkh(p0,p1); pb[j]=pkh(p2,p3);
        }
        lA=lA*cA+sA; lB=lB*cB+sB;
#pragma unroll
        for(int dt=0;dt<16;dt++){
            o[dt][0]*=cA; o[dt][1]*=cA; o[dt][2]*=cB; o[dt][3]*=cB;
        }

        // ---- O += P·(Vh+Vl) ----
#pragma unroll
        for(int kc=0;kc<4;kc++){
            uint32_t a4[4]={pa[2*kc],pb[2*kc],pa[2*kc+1],pb[2*kc+1]};
#pragma unroll
            for(int dp=0;dp<8;dp++){
                uint32_t vh[4],vl[4];
                ldm4t(vh, sb+2*(VHB+SWZH(kc*16+lr, dp*16+ldd)));
                ldm4t(vl, sb+2*(VLB+SWZH(kc*16+lr, dp*16+ldd)));
                mmaf(o[2*dp],a4,vh[0],vh[1]); mmaf(o[2*dp+1],a4,vh[2],vh[3]);
                mmaf(o[2*dp],a4,vl[0],vl[1]); mmaf(o[2*dp+1],a4,vl[2],vl[3]);
            }
        }
        __syncthreads();
        if(t+2<16){ load_kv(sb,gbase,t+2,t&1,tid); CPCOMMIT(); }
    }

    // ---- epilogue: normalize, store ----
    lA+=__shfl_xor_sync(0xffffffffu,lA,1); lA+=__shfl_xor_sync(0xffffffffu,lA,2);
    lB+=__shfl_xor_sync(0xffffffffu,lB,1); lB+=__shfl_xor_sync(0xffffffffu,lB,2);
    float iA=1.f/lA, iB=1.f/lB;
    int rA=qt*128+warp*16+(lane>>2), rB=rA+8, dc=2*(lane&3);
    float* obase=g_oh+(size_t)g*SEQ*DIM;
#pragma unroll
    for(int dt=0;dt<16;dt++){
        *(float2*)(obase+(size_t)rA*DIM+dt*8+dc)=make_float2(o[dt][0]*iA,o[dt][1]*iA);
        *(float2*)(obase+(size_t)rB*DIM+dt*8+dc)=make_float2(o[dt][2]*iB,o[dt][3]*iB);
    }
}

// ---------------- Kernel 3: head-mean + residual ----------------
__global__ void __launch_bounds__(256) reduce_kernel(const float* __restrict__ q, float* __restrict__ out)
{
    int i4=blockIdx.x*256+threadIdx.x;
    int bm=i4>>15, r4=i4&32767;
    const float4* oh4=(const float4*)g_oh;
    float sx=0,sy=0,sz=0,sw=0;
#pragma unroll
    for(int h=0;h<8;h++){
        float4 t=oh4[(size_t)(bm*8+h)*32768+r4];
        sx+=t.x; sy+=t.y; sz+=t.z; sw+=t.w;
    }
    float4 qv=((const float4*)q)[i4];
    ((float4*)out)[i4]=make_float4(qv.x+0.125f*sx,qv.y+0.125f*sy,qv.z+0.125f*sz,qv.w+0.125f*sw);
}

extern "C" void kernel_launch(void* const* d_in, const int* in_sizes, int n_in,
                              void* d_out, int out_size)
{
    const float *q=(const float*)d_in[0], *k=(const float*)d_in[1], *v=(const float*)d_in[2];
    const float *Wq=(const float*)d_in[3], *Wk=(const float*)d_in[4], *Wv=(const float*)d_in[5];
    float* out=(float*)d_out;
    cudaFuncSetAttribute(attn_kernel, cudaFuncAttributeMaxDynamicSharedMemorySize, ATTN_SMEM);
    proj_kernel<<<dim3(8,8,24),256>>>(q,k,v,Wq,Wk,Wv);
    attn_kernel<<<dim3(8,64),256,ATTN_SMEM>>>();
    reduce_kernel<<<1024,256>>>(q,out);
}

// round 6
// speedup vs baseline: 3.7487x; 1.3590x over previous
#include <cuda_runtime.h>
#include <cuda_fp16.h>
#include <cstdint>

#define SEQ 1024
#define DIM 128
#define NG 64

__device__ __half g_qh0[(size_t)NG*SEQ*DIM];
__device__ __half g_qh1[(size_t)NG*SEQ*DIM];
__device__ __half g_kh0[(size_t)NG*SEQ*DIM];
__device__ __half g_kh1[(size_t)NG*SEQ*DIM];
__device__ __half g_vh0[(size_t)NG*SEQ*DIM];
__device__ float  g_oh [(size_t)NG*SEQ*DIM];

// ---------------- helpers ----------------
__device__ __forceinline__ uint32_t s2u(const void* p){
    uint32_t a; asm("{ .reg .u64 t; cvta.to.shared.u64 t,%1; cvt.u32.u64 %0,t; }":"=r"(a):"l"(p)); return a;
}
__device__ __forceinline__ void cpa16(uint32_t d, const void* s){
    asm volatile("cp.async.cg.shared.global [%0],[%1],16;"::"r"(d),"l"(s));
}
#define CPCOMMIT() asm volatile("cp.async.commit_group;":::"memory")
#define CPWAIT1()  asm volatile("cp.async.wait_group 1;":::"memory")
#define CPWAIT0()  asm volatile("cp.async.wait_group 0;":::"memory")

__device__ __forceinline__ void ldm4(uint32_t r[4], uint32_t a){
    asm volatile("ldmatrix.sync.aligned.m8n8.x4.shared.b16 {%0,%1,%2,%3},[%4];"
        :"=r"(r[0]),"=r"(r[1]),"=r"(r[2]),"=r"(r[3]):"r"(a));
}
__device__ __forceinline__ void ldm4t(uint32_t r[4], uint32_t a){
    asm volatile("ldmatrix.sync.aligned.m8n8.x4.trans.shared.b16 {%0,%1,%2,%3},[%4];"
        :"=r"(r[0]),"=r"(r[1]),"=r"(r[2]),"=r"(r[3]):"r"(a));
}
__device__ __forceinline__ void mmaf(float c[4], const uint32_t a[4], uint32_t b0, uint32_t b1){
    asm volatile("mma.sync.aligned.m16n8k16.row.col.f32.f16.f16.f32 "
        "{%0,%1,%2,%3},{%4,%5,%6,%7},{%8,%9},{%0,%1,%2,%3};"
        :"+f"(c[0]),"+f"(c[1]),"+f"(c[2]),"+f"(c[3])
        :"r"(a[0]),"r"(a[1]),"r"(a[2]),"r"(a[3]),"r"(b0),"r"(b1));
}
__device__ __forceinline__ uint32_t pkh(float a, float b){
    __half2 h = __floats2half2_rn(a,b); return *(uint32_t*)&h;
}
__device__ __forceinline__ float fex2(float x){
    x = fmaxf(x, -120.f);
    float xf = floorf(x), f = x - xf;
    float p = fmaf(f, 0.0013333558f, 0.0096181291f);
    p = fmaf(f, p, 0.0555041087f);
    p = fmaf(f, p, 0.2402265070f);
    p = fmaf(f, p, 0.6931471806f);
    p = fmaf(f, p, 1.0f);
    return __int_as_float(((int)xf + 127) << 23) * p;
}
#define SWZH(r,d) ((r)*128 + ((((d)>>3)^((r)&7))<<3) + ((d)&7))

// ================= Kernel 1: projections on tensor cores =================
// Y[128x128 tile] = X[128s x 128c] * W[128c x 128e], fp16 hi/lo 3-combo.
// smem half-index map: XH 0 | XL 16384 | WH 32768 | WL 49152
#define PROJ_SMEM 131072

__global__ void __launch_bounds__(256) proj_kernel(
    const float* __restrict__ q, const float* __restrict__ k, const float* __restrict__ v,
    const float* __restrict__ Wq, const float* __restrict__ Wk, const float* __restrict__ Wv)
{
    extern __shared__ __half sm[];
    const uint32_t sb=s2u(sm);
    const int z=blockIdx.z, mat=z>>3, bm=z&7, m=bm&3;
    const float* X=(mat==0?q:mat==1?k:v)+(size_t)bm*SEQ*DIM;
    const float* W=(mat==0?Wq:mat==1?Wk:Wv)+(size_t)m*DIM*(8*DIM);
    const int tid=threadIdx.x, warp=tid>>5, lane=tid&31;
    const int bx=blockIdx.x, by=blockIdx.y;      // bx = head/e-tile, by = s-tile
    const int wm=warp&3, wn=warp>>2;
    const int lr=(lane&7)+((lane>>3)&1)*8;
    const int ldd=((lane>>4)&1)*8;

    // load + split X and W tiles into smem
#pragma unroll
    for(int i=0;i<16;i++){
        int idx=tid+i*256, row=idx>>5, c4=(idx&31)*4;
        float4 xv=*(const float4*)(X+(size_t)(by*128+row)*DIM+c4);
        __half2 h01=__floats2half2_rn(xv.x,xv.y), h23=__floats2half2_rn(xv.z,xv.w);
        float2 hx=__half22float2(h01), hz=__half22float2(h23);
        __half2 l01=__floats2half2_rn(xv.x-hx.x,xv.y-hx.y), l23=__floats2half2_rn(xv.z-hz.x,xv.w-hz.y);
        uint32_t off=2*SWZH(row,c4);
        *(uint32_t*)((char*)sm+off)      =*(uint32_t*)&h01;
        *(uint32_t*)((char*)sm+off+4)    =*(uint32_t*)&h23;
        *(uint32_t*)((char*)sm+32768+off)  =*(uint32_t*)&l01;
        *(uint32_t*)((char*)sm+32768+off+4)=*(uint32_t*)&l23;
    }
#pragma unroll
    for(int i=0;i<16;i++){
        int idx=tid+i*256, row=idx>>5, c4=(idx&31)*4;
        float4 wv=*(const float4*)(W+(size_t)row*(8*DIM)+bx*128+c4);
        __half2 h01=__floats2half2_rn(wv.x,wv.y), h23=__floats2half2_rn(wv.z,wv.w);
        float2 hx=__half22float2(h01), hz=__half22float2(h23);
        __half2 l01=__floats2half2_rn(wv.x-hx.x,wv.y-hx.y), l23=__floats2half2_rn(wv.z-hz.x,wv.w-hz.y);
        uint32_t off=2*SWZH(row,c4);
        *(uint32_t*)((char*)sm+65536+off)      =*(uint32_t*)&h01;
        *(uint32_t*)((char*)sm+65536+off+4)    =*(uint32_t*)&h23;
        *(uint32_t*)((char*)sm+98304+off)  =*(uint32_t*)&l01;
        *(uint32_t*)((char*)sm+98304+off+4)=*(uint32_t*)&l23;
    }
    __syncthreads();

    float acc[2][8][4];
#pragma unroll
    for(int i=0;i<2;i++)
#pragma unroll
        for(int j=0;j<8;j++)
#pragma unroll
            for(int p2=0;p2<4;p2++) acc[i][j][p2]=0.f;

#pragma unroll
    for(int kc=0;kc<8;kc++){
        uint32_t ah[2][4], al[2][4];
#pragma unroll
        for(int i=0;i<2;i++){
            ldm4(ah[i], sb+2*(SWZH(wm*32+i*16+lr, kc*16+ldd)));
            ldm4(al[i], sb+2*(16384+SWZH(wm*32+i*16+lr, kc*16+ldd)));
        }
#pragma unroll
        for(int np=0;np<4;np++){
            uint32_t wh[4], wl[4];
            ldm4t(wh, sb+2*(32768+SWZH(kc*16+lr, wn*64+np*16+ldd)));
            ldm4t(wl, sb+2*(49152+SWZH(kc*16+lr, wn*64+np*16+ldd)));
#pragma unroll
            for(int i=0;i<2;i++){
                mmaf(acc[i][2*np],ah[i],wh[0],wh[1]); mmaf(acc[i][2*np+1],ah[i],wh[2],wh[3]);
                mmaf(acc[i][2*np],ah[i],wl[0],wl[1]); mmaf(acc[i][2*np+1],ah[i],wl[2],wl[3]);
                mmaf(acc[i][2*np],al[i],wh[0],wh[1]); mmaf(acc[i][2*np+1],al[i],wh[2],wh[3]);
            }
        }
    }

    // epilogue: fp32 acc -> fp16 hi/lo splits (V: hi only)
    const int g=bm*8+bx;
    __half *d0, *d1; float sc;
    if(mat==0){ d0=g_qh0; d1=g_qh1; sc=0.12753102001968606f; }   // log2(e)/sqrt(128)
    else if(mat==1){ d0=g_kh0; d1=g_kh1; sc=1.f; }
    else { d0=g_vh0; d1=0; sc=1.f; }
    const int rbase=by*128+wm*32+(lane>>2);
    const int dbase=wn*64+2*(lane&3);
#pragma unroll
    for(int i=0;i<2;i++){
#pragma unroll
        for(int j=0;j<8;j++){
#pragma unroll
            for(int hrow=0;hrow<2;hrow++){
                int r=rbase+i*16+hrow*8, d=dbase+j*8;
                float x0=acc[i][j][2*hrow]*sc, x1=acc[i][j][2*hrow+1]*sc;
                __half2 h=__floats2half2_rn(x0,x1);
                size_t off=((size_t)(g*SEQ)+r)*DIM+d;
                *(__half2*)(d0+off)=h;
                if(d1){
                    float2 hf=__half22float2(h);
                    *(__half2*)(d1+off)=__floats2half2_rn(x0-hf.x,x1-hf.y);
                }
            }
        }
    }
}

// ================= Kernel 2: flash attention (fp16 splits, V hi-only) ======
// smem half map: Qh 0 | Ql 16384 | buffers at 32768 + b*24576 (Kh|Kl|Vh)
#define SM_KV 32768
#define ATTN_SMEM 163840

__device__ __forceinline__ void load_kv(uint32_t sb, size_t gbase, int t, int buf, int tid){
#pragma unroll
    for(int i=0;i<12;i++){
        int idx=tid+i*256, arr=idx>>10, rem=idx&1023, row=rem>>4, ch=rem&15;
        const __half* src;
        if(arr==0) src=g_kh0; else if(arr==1) src=g_kh1; else src=g_vh0;
        src += gbase+(size_t)(t*64+row)*DIM+ch*8;
        uint32_t dst=sb+2*(SM_KV+buf*24576+arr*8192+SWZH(row,ch*8));
        cpa16(dst,src);
    }
}

__global__ void __launch_bounds__(256,1) attn_kernel()
{
    extern __shared__ __half sm[];
    const uint32_t sb=s2u(sm);
    const int tid=threadIdx.x, warp=tid>>5, lane=tid&31;
    const int g=blockIdx.y, qt=blockIdx.x;
    const size_t gbase=(size_t)g*SEQ*DIM;
    const int lr=(lane&7)+((lane>>3)&1)*8;
    const int ldd=((lane>>4)&1)*8;

#pragma unroll
    for(int i=0;i<16;i++){
        int idx=tid+i*256, arr=idx>>11, rem=idx&2047, row=rem>>4, ch=rem&15;
        const __half* src=(arr? g_qh1:g_qh0)+gbase+(size_t)(qt*128+row)*DIM+ch*8;
        cpa16(sb+2*((arr?16384:0)+SWZH(row,ch*8)), src);
    }
    load_kv(sb,gbase,0,0,tid); CPCOMMIT();
    load_kv(sb,gbase,1,1,tid); CPCOMMIT();

    float o[16][4];
#pragma unroll
    for(int i=0;i<16;i++)
#pragma unroll
        for(int j2=0;j2<4;j2++) o[i][j2]=0.f;
    float mA=-1e30f, mB=-1e30f, lA=0.f, lB=0.f;

    for(int t=0;t<16;t++){
        if(t<15) CPWAIT1(); else CPWAIT0();
        __syncthreads();
        const uint32_t KHB=SM_KV+(t&1)*24576, KLB=KHB+8192, VHB=KHB+16384;

        float c[8][4];
#pragma unroll
        for(int j=0;j<8;j++)
#pragma unroll
            for(int i2=0;i2<4;i2++) c[j][i2]=0.f;
#pragma unroll
        for(int kc=0;kc<8;kc++){
            uint32_t ah[4],al[4];
            ldm4(ah, sb+2*(SWZH(warp*16+lr, kc*16+ldd)));
            ldm4(al, sb+2*(16384+SWZH(warp*16+lr, kc*16+ldd)));
#pragma unroll
            for(int np=0;np<4;np++){
                uint32_t kh[4],kl[4];
                ldm4(kh, sb+2*(KHB+SWZH(np*16+lr, kc*16+ldd)));
                ldm4(kl, sb+2*(KLB+SWZH(np*16+lr, kc*16+ldd)));
                mmaf(c[2*np],ah,kh[0],kh[2]); mmaf(c[2*np+1],ah,kh[1],kh[3]);
                mmaf(c[2*np],ah,kl[0],kl[2]); mmaf(c[2*np+1],ah,kl[1],kl[3]);
                mmaf(c[2*np],al,kh[0],kh[2]); mmaf(c[2*np+1],al,kh[1],kh[3]);
            }
        }

        float tA=-1e30f, tB=-1e30f;
#pragma unroll
        for(int j=0;j<8;j++){
            tA=fmaxf(tA,fmaxf(c[j][0],c[j][1]));
            tB=fmaxf(tB,fmaxf(c[j][2],c[j][3]));
        }
        tA=fmaxf(tA,__shfl_xor_sync(0xffffffffu,tA,1));
        tA=fmaxf(tA,__shfl_xor_sync(0xffffffffu,tA,2));
        tB=fmaxf(tB,__shfl_xor_sync(0xffffffffu,tB,1));
        tB=fmaxf(tB,__shfl_xor_sync(0xffffffffu,tB,2));
        float mnA=fmaxf(mA,tA), mnB=fmaxf(mB,tB);
        float cA=fex2(mA-mnA), cB=fex2(mB-mnB);
        mA=mnA; mB=mnB;
        uint32_t pa[8], pb[8];
        float sA=0.f, sB=0.f;
#pragma unroll
        for(int j=0;j<8;j++){
            float p0=fex2(c[j][0]-mnA), p1=fex2(c[j][1]-mnA);
            float p2=fex2(c[j][2]-mnB), p3=fex2(c[j][3]-mnB);
            sA+=p0+p1; sB+=p2+p3;
            pa[j]=pkh(p0,p1); pb[j]=pkh(p2,p3);
        }
        lA=lA*cA+sA; lB=lB*cB+sB;
#pragma unroll
        for(int dt=0;dt<16;dt++){
            o[dt][0]*=cA; o[dt][1]*=cA; o[dt][2]*=cB; o[dt][3]*=cB;
        }

#pragma unroll
        for(int kc=0;kc<4;kc++){
            uint32_t a4[4]={pa[2*kc],pb[2*kc],pa[2*kc+1],pb[2*kc+1]};
#pragma unroll
            for(int dp=0;dp<8;dp++){
                uint32_t vh[4];
                ldm4t(vh, sb+2*(VHB+SWZH(kc*16+lr, dp*16+ldd)));
                mmaf(o[2*dp],a4,vh[0],vh[1]); mmaf(o[2*dp+1],a4,vh[2],vh[3]);
            }
        }
        __syncthreads();
        if(t+2<16){ load_kv(sb,gbase,t+2,t&1,tid); CPCOMMIT(); }
    }

    lA+=__shfl_xor_sync(0xffffffffu,lA,1); lA+=__shfl_xor_sync(0xffffffffu,lA,2);
    lB+=__shfl_xor_sync(0xffffffffu,lB,1); lB+=__shfl_xor_sync(0xffffffffu,lB,2);
    float iA=1.f/lA, iB=1.f/lB;
    int rA=qt*128+warp*16+(lane>>2), rB=rA+8, dc=2*(lane&3);
    float* obase=g_oh+(size_t)g*SEQ*DIM;
#pragma unroll
    for(int dt=0;dt<16;dt++){
        *(float2*)(obase+(size_t)rA*DIM+dt*8+dc)=make_float2(o[dt][0]*iA,o[dt][1]*iA);
        *(float2*)(obase+(size_t)rB*DIM+dt*8+dc)=make_float2(o[dt][2]*iB,o[dt][3]*iB);
    }
}

// ================= Kernel 3: head-mean + residual =================
__global__ void __launch_bounds__(256) reduce_kernel(const float* __restrict__ q, float* __restrict__ out)
{
    int i4=blockIdx.x*256+threadIdx.x;
    int bm=i4>>15, r4=i4&32767;
    const float4* oh4=(const float4*)g_oh;
    float sx=0,sy=0,sz=0,sw=0;
#pragma unroll
    for(int h=0;h<8;h++){
        float4 t=oh4[(size_t)(bm*8+h)*32768+r4];
        sx+=t.x; sy+=t.y; sz+=t.z; sw+=t.w;
    }
    float4 qv=((const float4*)q)[i4];
    ((float4*)out)[i4]=make_float4(qv.x+0.125f*sx,qv.y+0.125f*sy,qv.z+0.125f*sz,qv.w+0.125f*sw);
}

extern "C" void kernel_launch(void* const* d_in, const int* in_sizes, int n_in,
                              void* d_out, int out_size)
{
    const float *q=(const float*)d_in[0], *k=(const float*)d_in[1], *v=(const float*)d_in[2];
    const float *Wq=(const float*)d_in[3], *Wk=(const float*)d_in[4], *Wv=(const float*)d_in[5];
    float* out=(float*)d_out;
    cudaFuncSetAttribute(proj_kernel, cudaFuncAttributeMaxDynamicSharedMemorySize, PROJ_SMEM);
    cudaFuncSetAttribute(attn_kernel, cudaFuncAttributeMaxDynamicSharedMemorySize, ATTN_SMEM);
    proj_kernel<<<dim3(8,8,24),256,PROJ_SMEM>>>(q,k,v,Wq,Wk,Wv);
    attn_kernel<<<dim3(8,64),256,ATTN_SMEM>>>();
    reduce_kernel<<<1024,256>>>(q,out);
}

// round 8
// speedup vs baseline: 3.7974x; 1.0130x over previous
#include <cuda_runtime.h>
#include <cuda_fp16.h>
#include <cstdint>

#define SEQ 1024
#define DIM 128
#define NG 64

__device__ __half g_qh0[(size_t)NG*SEQ*DIM];
__device__ __half g_qh1[(size_t)NG*SEQ*DIM];
__device__ __half g_kh0[(size_t)NG*SEQ*DIM];
__device__ __half g_kh1[(size_t)NG*SEQ*DIM];
__device__ __half g_vh0[(size_t)NG*SEQ*DIM];
__device__ __half g_oh [(size_t)NG*SEQ*DIM];

// ---------------- helpers ----------------
__device__ __forceinline__ uint32_t s2u(const void* p){
    uint32_t a; asm("{ .reg .u64 t; cvta.to.shared.u64 t,%1; cvt.u32.u64 %0,t; }":"=r"(a):"l"(p)); return a;
}
__device__ __forceinline__ void cpa16(uint32_t d, const void* s){
    asm volatile("cp.async.cg.shared.global [%0],[%1],16;"::"r"(d),"l"(s));
}
#define CPCOMMIT() asm volatile("cp.async.commit_group;":::"memory")
#define CPWAIT1()  asm volatile("cp.async.wait_group 1;":::"memory")
#define CPWAIT0()  asm volatile("cp.async.wait_group 0;":::"memory")

__device__ __forceinline__ void ldm4(uint32_t r[4], uint32_t a){
    asm volatile("ldmatrix.sync.aligned.m8n8.x4.shared.b16 {%0,%1,%2,%3},[%4];"
        :"=r"(r[0]),"=r"(r[1]),"=r"(r[2]),"=r"(r[3]):"r"(a));
}
__device__ __forceinline__ void ldm4t(uint32_t r[4], uint32_t a){
    asm volatile("ldmatrix.sync.aligned.m8n8.x4.trans.shared.b16 {%0,%1,%2,%3},[%4];"
        :"=r"(r[0]),"=r"(r[1]),"=r"(r[2]),"=r"(r[3]):"r"(a));
}
__device__ __forceinline__ void mmaf(float c[4], const uint32_t a[4], uint32_t b0, uint32_t b1){
    asm volatile("mma.sync.aligned.m16n8k16.row.col.f32.f16.f16.f32 "
        "{%0,%1,%2,%3},{%4,%5,%6,%7},{%8,%9},{%0,%1,%2,%3};"
        :"+f"(c[0]),"+f"(c[1]),"+f"(c[2]),"+f"(c[3])
        :"r"(a[0]),"r"(a[1]),"r"(a[2]),"r"(a[3]),"r"(b0),"r"(b1));
}
__device__ __forceinline__ uint32_t pkh(float a, float b){
    __half2 h = __floats2half2_rn(a,b); return *(uint32_t*)&h;
}
__device__ __forceinline__ float fex2(float x){
    x = fmaxf(x, -120.f);
    float xf = floorf(x), f = x - xf;
    float p = fmaf(f, 0.0013333558f, 0.0096181291f);
    p = fmaf(f, p, 0.0555041087f);
    p = fmaf(f, p, 0.2402265070f);
    p = fmaf(f, p, 0.6931471806f);
    p = fmaf(f, p, 1.0f);
    return __int_as_float(((int)xf + 127) << 23) * p;
}
#define SWZH(r,d) ((r)*128 + ((((d)>>3)^((r)&7))<<3) + ((d)&7))

// split a float4 into hi/lo half2 pairs and store to smem (byte offsets)
__device__ __forceinline__ void split_store(__half* sm, uint32_t offH, uint32_t offL, float4 t){
    __half2 h01=__floats2half2_rn(t.x,t.y), h23=__floats2half2_rn(t.z,t.w);
    float2 f01=__half22float2(h01), f23=__half22float2(h23);
    __half2 l01=__floats2half2_rn(t.x-f01.x,t.y-f01.y), l23=__floats2half2_rn(t.z-f23.x,t.w-f23.y);
    *(uint32_t*)((char*)sm+offH)  =*(uint32_t*)&h01;
    *(uint32_t*)((char*)sm+offH+4)=*(uint32_t*)&h23;
    *(uint32_t*)((char*)sm+offL)  =*(uint32_t*)&l01;
    *(uint32_t*)((char*)sm+offL+4)=*(uint32_t*)&l23;
}

// ================= Kernel 1a: Q/K projections (3-combo, K-chunk pipelined) ===
// smem byte map: XH 0 | XL 32768 | WH 65536 | WL 98304   (128 KB)
#define PROJQK_SMEM 131072
__global__ void __launch_bounds__(256) proj_qk_kernel(
    const float* __restrict__ Xq, const float* __restrict__ Xk,
    const float* __restrict__ Wq, const float* __restrict__ Wk)
{
    extern __shared__ __half sm[];
    const uint32_t sb=s2u(sm);
    const int z=blockIdx.z, mat=z>>3, bm=z&7, m=bm&3;
    const float* X=(mat? Xk:Xq)+(size_t)bm*SEQ*DIM;
    const float* W=(mat? Wk:Wq)+(size_t)m*DIM*(8*DIM);
    const int tid=threadIdx.x, warp=tid>>5, lane=tid&31;
    const int bx=blockIdx.x, by=blockIdx.y;
    const int wm=warp&3, wn=warp>>2;
    const int lr=(lane&7)+((lane>>3)&1)*8;
    const int ldd=((lane>>4)&1)*8;

    auto loadC=[&](float4 xv[4], float4 wv[4], int ch){
#pragma unroll
        for(int i=0;i<4;i++){
            int idx=tid+i*256;
            xv[i]=*(const float4*)(X+(size_t)(by*128+(idx>>3))*DIM+(idx&7)*4+ch*32);
            wv[i]=*(const float4*)(W+(size_t)((idx>>5)+ch*32)*(8*DIM)+bx*128+(idx&31)*4);
        }
    };
    auto storeC=[&](const float4 xv[4], const float4 wv[4], int ch){
#pragma unroll
        for(int i=0;i<4;i++){
            int idx=tid+i*256;
            uint32_t xo=2*SWZH(idx>>3,(idx&7)*4+ch*32);
            split_store(sm, xo, 32768+xo, xv[i]);
            uint32_t wo=2*SWZH((idx>>5)+ch*32,(idx&31)*4);
            split_store(sm, 65536+wo, 98304+wo, wv[i]);
        }
    };

    float acc[2][8][4];
#pragma unroll
    for(int i=0;i<2;i++)
#pragma unroll
        for(int j=0;j<8;j++)
#pragma unroll
            for(int p2=0;p2<4;p2++) acc[i][j][p2]=0.f;

    float4 xv[4], wv[4];
    loadC(xv,wv,0); storeC(xv,wv,0); __syncthreads();
#pragma unroll
    for(int ch=0;ch<4;ch++){
        if(ch<3) loadC(xv,wv,ch+1);
#pragma unroll
        for(int kk=0;kk<2;kk++){
            int kc=2*ch+kk;
            uint32_t ah[2][4], al[2][4];
#pragma unroll
            for(int i=0;i<2;i++){
                ldm4(ah[i], sb+2*(SWZH(wm*32+i*16+lr, kc*16+ldd)));
                ldm4(al[i], sb+2*(16384+SWZH(wm*32+i*16+lr, kc*16+ldd)));
            }
#pragma unroll
            for(int np=0;np<4;np++){
                uint32_t wh[4], wl[4];
                ldm4t(wh, sb+2*(32768+SWZH(kc*16+lr, wn*64+np*16+ldd)));
                ldm4t(wl, sb+2*(49152+SWZH(kc*16+lr, wn*64+np*16+ldd)));
#pragma unroll
                for(int i=0;i<2;i++){
                    mmaf(acc[i][2*np],ah[i],wh[0],wh[1]); mmaf(acc[i][2*np+1],ah[i],wh[2],wh[3]);
                    mmaf(acc[i][2*np],ah[i],wl[0],wl[1]); mmaf(acc[i][2*np+1],ah[i],wl[2],wl[3]);
                    mmaf(acc[i][2*np],al[i],wh[0],wh[1]); mmaf(acc[i][2*np+1],al[i],wh[2],wh[3]);
                }
            }
        }
        if(ch<3){ storeC(xv,wv,ch+1); __syncthreads(); }
    }

    const int g=bm*8+bx;
    __half* d0 = mat? g_kh0 : g_qh0;
    __half* d1 = mat? g_kh1 : g_qh1;
    const float sc = mat? 1.f : 0.12753102001968606f;   // log2(e)/sqrt(128)
    const int rbase=by*128+wm*32+(lane>>2);
    const int dbase=wn*64+2*(lane&3);
#pragma unroll
    for(int i=0;i<2;i++)
#pragma unroll
        for(int j=0;j<8;j++)
#pragma unroll
            for(int hr=0;hr<2;hr++){
                int r=rbase+i*16+hr*8, d=dbase+j*8;
                float x0=acc[i][j][2*hr]*sc, x1=acc[i][j][2*hr+1]*sc;
                __half2 h=__floats2half2_rn(x0,x1);
                size_t off=((size_t)(g*SEQ)+r)*DIM+d;
                *(__half2*)(d0+off)=h;
                float2 hf=__half22float2(h);
                *(__half2*)(d1+off)=__floats2half2_rn(x0-hf.x,x1-hf.y);
            }
}

// ================= Kernel 1b: V projection (hh-only, 64 KB smem) ============
// smem byte map: XH 0 | WH 32768
#define PROJV_SMEM 65536
__global__ void __launch_bounds__(256) proj_v_kernel(
    const float* __restrict__ Xv, const float* __restrict__ Wv)
{
    extern __shared__ __half sm[];
    const uint32_t sb=s2u(sm);
    const int bm=blockIdx.z, m=bm&3;
    const float* X=Xv+(size_t)bm*SEQ*DIM;
    const float* W=Wv+(size_t)m*DIM*(8*DIM);
    const int tid=threadIdx.x, warp=tid>>5, lane=tid&31;
    const int bx=blockIdx.x, by=blockIdx.y;
    const int wm=warp&3, wn=warp>>2;
    const int lr=(lane&7)+((lane>>3)&1)*8;
    const int ldd=((lane>>4)&1)*8;

    auto loadC=[&](float4 xv[4], float4 wv[4], int ch){
#pragma unroll
        for(int i=0;i<4;i++){
            int idx=tid+i*256;
            xv[i]=*(const float4*)(X+(size_t)(by*128+(idx>>3))*DIM+(idx&7)*4+ch*32);
            wv[i]=*(const float4*)(W+(size_t)((idx>>5)+ch*32)*(8*DIM)+bx*128+(idx&31)*4);
        }
    };
    auto storeC=[&](const float4 xv[4], const float4 wv[4], int ch){
#pragma unroll
        for(int i=0;i<4;i++){
            int idx=tid+i*256;
            float4 t=xv[i];
            __half2 h01=__floats2half2_rn(t.x,t.y), h23=__floats2half2_rn(t.z,t.w);
            uint32_t xo=2*SWZH(idx>>3,(idx&7)*4+ch*32);
            *(uint32_t*)((char*)sm+xo)=*(uint32_t*)&h01; *(uint32_t*)((char*)sm+xo+4)=*(uint32_t*)&h23;
            t=wv[i];
            h01=__floats2half2_rn(t.x,t.y); h23=__floats2half2_rn(t.z,t.w);
            uint32_t wo=2*SWZH((idx>>5)+ch*32,(idx&31)*4);
            *(uint32_t*)((char*)sm+32768+wo)=*(uint32_t*)&h01; *(uint32_t*)((char*)sm+32768+wo+4)=*(uint32_t*)&h23;
        }
    };

    float acc[2][8][4];
#pragma unroll
    for(int i=0;i<2;i++)
#pragma unroll
        for(int j=0;j<8;j++)
#pragma unroll
            for(int p2=0;p2<4;p2++) acc[i][j][p2]=0.f;

    float4 xv[4], wv[4];
    loadC(xv,wv,0); storeC(xv,wv,0); __syncthreads();
#pragma unroll
    for(int ch=0;ch<4;ch++){
        if(ch<3) loadC(xv,wv,ch+1);
#pragma unroll
        for(int kk=0;kk<2;kk++){
            int kc=2*ch+kk;
            uint32_t ah[2][4];
#pragma unroll
            for(int i=0;i<2;i++)
                ldm4(ah[i], sb+2*(SWZH(wm*32+i*16+lr, kc*16+ldd)));
#pragma unroll
            for(int np=0;np<4;np++){
                uint32_t wh[4];
                ldm4t(wh, sb+2*(16384+SWZH(kc*16+lr, wn*64+np*16+ldd)));
#pragma unroll
                for(int i=0;i<2;i++){
                    mmaf(acc[i][2*np],ah[i],wh[0],wh[1]); mmaf(acc[i][2*np+1],ah[i],wh[2],wh[3]);
                }
            }
        }
        if(ch<3){ storeC(xv,wv,ch+1); __syncthreads(); }
    }

    const int g=bm*8+bx;
    const int rbase=by*128+wm*32+(lane>>2);
    const int dbase=wn*64+2*(lane&3);
#pragma unroll
    for(int i=0;i<2;i++)
#pragma unroll
        for(int j=0;j<8;j++)
#pragma unroll
            for(int hr=0;hr<2;hr++){
                int r=rbase+i*16+hr*8, d=dbase+j*8;
                size_t off=((size_t)(g*SEQ)+r)*DIM+d;
                *(__half2*)(g_vh0+off)=__floats2half2_rn(acc[i][j][2*hr],acc[i][j][2*hr+1]);
            }
}

// ================= Kernel 2: flash attention (Q-frags hoisted) ==============
// smem half map: Qh 0 | Ql 16384 | buffers at 32768 + b*24576 (Kh|Kl|Vh)
#define SM_KV 32768
#define ATTN_SMEM 163840

__device__ __forceinline__ void load_kv(uint32_t sb, size_t gbase, int t, int buf, int tid){
#pragma unroll
    for(int i=0;i<12;i++){
        int idx=tid+i*256, arr=idx>>10, rem=idx&1023, row=rem>>4, ch=rem&15;
        const __half* src;
        if(arr==0) src=g_kh0; else if(arr==1) src=g_kh1; else src=g_vh0;
        src += gbase+(size_t)(t*64+row)*DIM+ch*8;
        uint32_t dst=sb+2*(SM_KV+buf*24576+arr*8192+SWZH(row,ch*8));
        cpa16(dst,src);
    }
}

__global__ void __launch_bounds__(256,1) attn_kernel()
{
    extern __shared__ __half sm[];
    const uint32_t sb=s2u(sm);
    const int tid=threadIdx.x, warp=tid>>5, lane=tid&31;
    const int g=blockIdx.y, qt=blockIdx.x;
    const size_t gbase=(size_t)g*SEQ*DIM;
    const int lr=(lane&7)+((lane>>3)&1)*8;
    const int ldd=((lane>>4)&1)*8;

#pragma unroll
    for(int i=0;i<16;i++){
        int idx=tid+i*256, arr=idx>>11, rem=idx&2047, row=rem>>4, ch=rem&15;
        const __half* src=(arr? g_qh1:g_qh0)+gbase+(size_t)(qt*128+row)*DIM+ch*8;
        cpa16(sb+2*((arr?16384:0)+SWZH(row,ch*8)), src);
    }
    load_kv(sb,gbase,0,0,tid); CPCOMMIT();   // group A: Q + kv0
    load_kv(sb,gbase,1,1,tid); CPCOMMIT();   // group B: kv1

    CPWAIT1();                                // group A done
    __syncthreads();
    // hoist Q fragments (invariant across key tiles)
    uint32_t qah[8][4], qal[8][4];
#pragma unroll
    for(int kc=0;kc<8;kc++){
        ldm4(qah[kc], sb+2*(SWZH(warp*16+lr, kc*16+ldd)));
        ldm4(qal[kc], sb+2*(16384+SWZH(warp*16+lr, kc*16+ldd)));
    }

    float o[16][4];
#pragma unroll
    for(int i=0;i<16;i++)
#pragma unroll
        for(int j2=0;j2<4;j2++) o[i][j2]=0.f;
    float mA=-1e30f, mB=-1e30f, lA=0.f, lB=0.f;

    for(int t=0;t<16;t++){
        if(t<15) CPWAIT1(); else CPWAIT0();
        __syncthreads();
        const uint32_t KHB=SM_KV+(t&1)*24576, KLB=KHB+8192, VHB=KHB+16384;

        float c[8][4];
#pragma unroll
        for(int j=0;j<8;j++)
#pragma unroll
            for(int i2=0;i2<4;i2++) c[j][i2]=0.f;
#pragma unroll
        for(int kc=0;kc<8;kc++){
#pragma unroll
            for(int np=0;np<4;np++){
                uint32_t kh[4],kl[4];
                ldm4(kh, sb+2*(KHB+SWZH(np*16+lr, kc*16+ldd)));
                ldm4(kl, sb+2*(KLB+SWZH(np*16+lr, kc*16+ldd)));
                mmaf(c[2*np],qah[kc],kh[0],kh[2]); mmaf(c[2*np+1],qah[kc],kh[1],kh[3]);
                mmaf(c[2*np],qah[kc],kl[0],kl[2]); mmaf(c[2*np+1],qah[kc],kl[1],kl[3]);
                mmaf(c[2*np],qal[kc],kh[0],kh[2]); mmaf(c[2*np+1],qal[kc],kh[1],kh[3]);
            }
        }

        float tA=-1e30f, tB=-1e30f;
#pragma unroll
        for(int j=0;j<8;j++){
            tA=fmaxf(tA,fmaxf(c[j][0],c[j][1]));
            tB=fmaxf(tB,fmaxf(c[j][2],c[j][3]));
        }
        tA=fmaxf(tA,__shfl_xor_sync(0xffffffffu,tA,1));
        tA=fmaxf(tA,__shfl_xor_sync(0xffffffffu,tA,2));
        tB=fmaxf(tB,__shfl_xor_sync(0xffffffffu,tB,1));
        tB=fmaxf(tB,__shfl_xor_sync(0xffffffffu,tB,2));
        float mnA=fmaxf(mA,tA), mnB=fmaxf(mB,tB);
        float cA=fex2(mA-mnA), cB=fex2(mB-mnB);
        mA=mnA; mB=mnB;
        uint32_t pa[8], pb[8];
        float sA=0.f, sB=0.f;
#pragma unroll
        for(int j=0;j<8;j++){
            float p0=fex2(c[j][0]-mnA), p1=fex2(c[j][1]-mnA);
            float p2=fex2(c[j][2]-mnB), p3=fex2(c[j][3]-mnB);
            sA+=p0+p1; sB+=p2+p3;
            pa[j]=pkh(p0,p1); pb[j]=pkh(p2,p3);
        }
        lA=lA*cA+sA; lB=lB*cB+sB;
        if(cA!=1.f){
#pragma unroll
            for(int dt=0;dt<16;dt++){ o[dt][0]*=cA; o[dt][1]*=cA; }
        }
        if(cB!=1.f){
#pragma unroll
            for(int dt=0;dt<16;dt++){ o[dt][2]*=cB; o[dt][3]*=cB; }
        }

#pragma unroll
        for(int kc=0;kc<4;kc++){
            uint32_t a4[4]={pa[2*kc],pb[2*kc],pa[2*kc+1],pb[2*kc+1]};
#pragma unroll
            for(int dp=0;dp<8;dp++){
                uint32_t vh[4];
                ldm4t(vh, sb+2*(VHB+SWZH(kc*16+lr, dp*16+ldd)));
                mmaf(o[2*dp],a4,vh[0],vh[1]); mmaf(o[2*dp+1],a4,vh[2],vh[3]);
            }
        }
        __syncthreads();
        if(t+2<16){ load_kv(sb,gbase,t+2,t&1,tid); CPCOMMIT(); }
    }

    lA+=__shfl_xor_sync(0xffffffffu,lA,1); lA+=__shfl_xor_sync(0xffffffffu,lA,2);
    lB+=__shfl_xor_sync(0xffffffffu,lB,1); lB+=__shfl_xor_sync(0xffffffffu,lB,2);
    float iA=1.f/lA, iB=1.f/lB;
    int rA=qt*128+warp*16+(lane>>2), rB=rA+8, dc=2*(lane&3);
    __half* obase=g_oh+gbase;
#pragma unroll
    for(int dt=0;dt<16;dt++){
        *(__half2*)(obase+(size_t)rA*DIM+dt*8+dc)=__floats2half2_rn(o[dt][0]*iA,o[dt][1]*iA);
        *(__half2*)(obase+(size_t)rB*DIM+dt*8+dc)=__floats2half2_rn(o[dt][2]*iB,o[dt][3]*iB);
    }
}

// ================= Kernel 3: head-mean + residual (fp16 g_oh) ===============
__global__ void __launch_bounds__(256) reduce_kernel(const float* __restrict__ q, float* __restrict__ out)
{
    int i4=blockIdx.x*256+threadIdx.x;     // float4 index, 262144 total
    int bm=i4>>15, r4=i4&32767;
    float sx=0,sy=0,sz=0,sw=0;
#pragma unroll
    for(int h=0;h<8;h++){
        uint2 v=*(const uint2*)(g_oh+((size_t)(bm*8+h))*131072+(size_t)r4*4);
        __half2 a=*(__half2*)&v.x, b=*(__half2*)&v.y;
        float2 fa=__half22float2(a), fb=__half22float2(b);
        sx+=fa.x; sy+=fa.y; sz+=fb.x; sw+=fb.y;
    }
    float4 qv=((const float4*)q)[i4];
    ((float4*)out)[i4]=make_float4(qv.x+0.125f*sx,qv.y+0.125f*sy,qv.z+0.125f*sz,qv.w+0.125f*sw);
}

extern "C" void kernel_launch(void* const* d_in, const int* in_sizes, int n_in,
                              void* d_out, int out_size)
{
    const float *q=(const float*)d_in[0], *k=(const float*)d_in[1], *v=(const float*)d_in[2];
    const float *Wq=(const float*)d_in[3], *Wk=(const float*)d_in[4], *Wv=(const float*)d_in[5];
    float* out=(float*)d_out;
    cudaFuncSetAttribute(proj_qk_kernel, cudaFuncAttributeMaxDynamicSharedMemorySize, PROJQK_SMEM);
    cudaFuncSetAttribute(proj_v_kernel, cudaFuncAttributeMaxDynamicSharedMemorySize, PROJV_SMEM);
    cudaFuncSetAttribute(attn_kernel, cudaFuncAttributeMaxDynamicSharedMemorySize, ATTN_SMEM);
    proj_qk_kernel<<<dim3(8,8,16),256,PROJQK_SMEM>>>(q,k,Wq,Wk);
    proj_v_kernel <<<dim3(8,8,8),256,PROJV_SMEM>>>(v,Wv);
    attn_kernel<<<dim3(8,64),256,ATTN_SMEM>>>();
    reduce_kernel<<<1024,256>>>(q,out);
}

// round 9
// speedup vs baseline: 4.3689x; 1.1505x over previous
#include <cuda_runtime.h>
#include <cuda_fp16.h>
#include <cstdint>

#define SEQ 1024
#define DIM 128
#define NG 64

__device__ __half g_qh0[(size_t)NG*SEQ*DIM];
__device__ __half g_qh1[(size_t)NG*SEQ*DIM];
__device__ __half g_kh0[(size_t)NG*SEQ*DIM];
__device__ __half g_kh1[(size_t)NG*SEQ*DIM];
__device__ __half g_vh0[(size_t)NG*SEQ*DIM];
__device__ __half g_oh [(size_t)NG*SEQ*DIM];

// ---------------- helpers ----------------
__device__ __forceinline__ uint32_t s2u(const void* p){
    uint32_t a; asm("{ .reg .u64 t; cvta.to.shared.u64 t,%1; cvt.u32.u64 %0,t; }":"=r"(a):"l"(p)); return a;
}
__device__ __forceinline__ void cpa16(uint32_t d, const void* s){
    asm volatile("cp.async.cg.shared.global [%0],[%1],16;"::"r"(d),"l"(s));
}
#define CPCOMMIT() asm volatile("cp.async.commit_group;":::"memory")
#define CPWAIT1()  asm volatile("cp.async.wait_group 1;":::"memory")
#define CPWAIT0()  asm volatile("cp.async.wait_group 0;":::"memory")

__device__ __forceinline__ void ldm4(uint32_t r[4], uint32_t a){
    asm volatile("ldmatrix.sync.aligned.m8n8.x4.shared.b16 {%0,%1,%2,%3},[%4];"
        :"=r"(r[0]),"=r"(r[1]),"=r"(r[2]),"=r"(r[3]):"r"(a));
}
__device__ __forceinline__ void ldm4t(uint32_t r[4], uint32_t a){
    asm volatile("ldmatrix.sync.aligned.m8n8.x4.trans.shared.b16 {%0,%1,%2,%3},[%4];"
        :"=r"(r[0]),"=r"(r[1]),"=r"(r[2]),"=r"(r[3]):"r"(a));
}
__device__ __forceinline__ void mmaf(float c[4], const uint32_t a[4], uint32_t b0, uint32_t b1){
    asm volatile("mma.sync.aligned.m16n8k16.row.col.f32.f16.f16.f32 "
        "{%0,%1,%2,%3},{%4,%5,%6,%7},{%8,%9},{%0,%1,%2,%3};"
        :"+f"(c[0]),"+f"(c[1]),"+f"(c[2]),"+f"(c[3])
        :"r"(a[0]),"r"(a[1]),"r"(a[2]),"r"(a[3]),"r"(b0),"r"(b1));
}
__device__ __forceinline__ uint32_t pkh(float a, float b){
    __half2 h = __floats2half2_rn(a,b); return *(uint32_t*)&h;
}
__device__ __forceinline__ float fex2(float x){
    x = fmaxf(x, -120.f);
    float xf = floorf(x), f = x - xf;
    float p = fmaf(f, 0.0013333558f, 0.0096181291f);
    p = fmaf(f, p, 0.0555041087f);
    p = fmaf(f, p, 0.2402265070f);
    p = fmaf(f, p, 0.6931471806f);
    p = fmaf(f, p, 1.0f);
    return __int_as_float(((int)xf + 127) << 23) * p;
}
#define SWZH(r,d) ((r)*128 + ((((d)>>3)^((r)&7))<<3) + ((d)&7))

__device__ __forceinline__ void split_store(__half* sm, uint32_t offH, uint32_t offL, float4 t){
    __half2 h01=__floats2half2_rn(t.x,t.y), h23=__floats2half2_rn(t.z,t.w);
    float2 f01=__half22float2(h01), f23=__half22float2(h23);
    __half2 l01=__floats2half2_rn(t.x-f01.x,t.y-f01.y), l23=__floats2half2_rn(t.z-f23.x,t.w-f23.y);
    *(uint32_t*)((char*)sm+offH)  =*(uint32_t*)&h01;
    *(uint32_t*)((char*)sm+offH+4)=*(uint32_t*)&h23;
    *(uint32_t*)((char*)sm+offL)  =*(uint32_t*)&l01;
    *(uint32_t*)((char*)sm+offL+4)=*(uint32_t*)&l23;
}

// ================= Kernel 1a: Q/K projections, 64-row tiles, 2 CTAs/SM ======
// smem bytes: XH 0 (16K) | XL 16384 | WH 32768 (32K) | WL 65536  -> 96 KB
#define PROJQK_SMEM 98304
__global__ void __launch_bounds__(256,2) proj_qk_kernel(
    const float* __restrict__ Xq, const float* __restrict__ Xk,
    const float* __restrict__ Wq, const float* __restrict__ Wk)
{
    extern __shared__ __half sm[];
    const uint32_t sb=s2u(sm);
    const int z=blockIdx.z, mat=z>>3, bm=z&7, m=bm&3;
    const float* X=(mat? Xk:Xq)+(size_t)bm*SEQ*DIM;
    const float* W=(mat? Wk:Wq)+(size_t)m*DIM*(8*DIM);
    const int tid=threadIdx.x, warp=tid>>5, lane=tid&31;
    const int bx=blockIdx.x, by=blockIdx.y;      // bx = head, by = 64-row s-tile
    const int wm=warp&3, wn=warp>>2;             // 16-row group, 64-col group
    const int lr=(lane&7)+((lane>>3)&1)*8;
    const int ldd=((lane>>4)&1)*8;

    // X: 64x128 fp32 -> hi/lo
#pragma unroll
    for(int i=0;i<8;i++){
        int idx=tid+i*256, row=idx>>5, c4=(idx&31)*4;
        float4 xv=*(const float4*)(X+(size_t)(by*64+row)*DIM+c4);
        uint32_t xo=2*SWZH(row,c4);
        split_store(sm, xo, 16384+xo, xv);
    }
    // W: 128x128 fp32 -> hi/lo
#pragma unroll
    for(int i=0;i<16;i++){
        int idx=tid+i*256, row=idx>>5, c4=(idx&31)*4;
        float4 wv=*(const float4*)(W+(size_t)row*(8*DIM)+bx*128+c4);
        uint32_t wo=2*SWZH(row,c4);
        split_store(sm, 32768+wo, 65536+wo, wv);
    }
    __syncthreads();

    float acc[8][4];
#pragma unroll
    for(int j=0;j<8;j++)
#pragma unroll
        for(int p2=0;p2<4;p2++) acc[j][p2]=0.f;

#pragma unroll
    for(int kc=0;kc<8;kc++){
        uint32_t ah[4], al[4];
        ldm4(ah, sb+2*(SWZH(wm*16+lr, kc*16+ldd)));
        ldm4(al, sb+2*(8192+SWZH(wm*16+lr, kc*16+ldd)));
#pragma unroll
        for(int np=0;np<4;np++){
            uint32_t wh[4], wl[4];
            ldm4t(wh, sb+2*(16384+SWZH(kc*16+lr, wn*64+np*16+ldd)));
            ldm4t(wl, sb+2*(32768+SWZH(kc*16+lr, wn*64+np*16+ldd)));
            mmaf(acc[2*np],ah,wh[0],wh[1]); mmaf(acc[2*np+1],ah,wh[2],wh[3]);
            mmaf(acc[2*np],ah,wl[0],wl[1]); mmaf(acc[2*np+1],ah,wl[2],wl[3]);
            mmaf(acc[2*np],al,wh[0],wh[1]); mmaf(acc[2*np+1],al,wh[2],wh[3]);
        }
    }

    const int g=bm*8+bx;
    __half* d0 = mat? g_kh0 : g_qh0;
    __half* d1 = mat? g_kh1 : g_qh1;
    const float sc = mat? 1.f : 0.12753102001968606f;   // log2(e)/sqrt(128)
    const int rbase=by*64+wm*16+(lane>>2);
    const int dbase=wn*64+2*(lane&3);
#pragma unroll
    for(int j=0;j<8;j++)
#pragma unroll
        for(int hr=0;hr<2;hr++){
            int r=rbase+hr*8, d=dbase+j*8;
            float x0=acc[j][2*hr]*sc, x1=acc[j][2*hr+1]*sc;
            __half2 h=__floats2half2_rn(x0,x1);
            size_t off=((size_t)(g*SEQ)+r)*DIM+d;
            *(__half2*)(d0+off)=h;
            float2 hf=__half22float2(h);
            *(__half2*)(d1+off)=__floats2half2_rn(x0-hf.x,x1-hf.y);
        }
}

// ================= Kernel 1b: V projection, hh-only, 64-row tiles ===========
// smem bytes: XH 0 (16K) | WH 16384 (32K)  -> 48 KB
#define PROJV_SMEM 49152
__global__ void __launch_bounds__(256,2) proj_v_kernel(
    const float* __restrict__ Xv, const float* __restrict__ Wv)
{
    extern __shared__ __half sm[];
    const uint32_t sb=s2u(sm);
    const int bm=blockIdx.z, m=bm&3;
    const float* X=Xv+(size_t)bm*SEQ*DIM;
    const float* W=Wv+(size_t)m*DIM*(8*DIM);
    const int tid=threadIdx.x, warp=tid>>5, lane=tid&31;
    const int bx=blockIdx.x, by=blockIdx.y;
    const int wm=warp&3, wn=warp>>2;
    const int lr=(lane&7)+((lane>>3)&1)*8;
    const int ldd=((lane>>4)&1)*8;

#pragma unroll
    for(int i=0;i<8;i++){
        int idx=tid+i*256, row=idx>>5, c4=(idx&31)*4;
        float4 t=*(const float4*)(X+(size_t)(by*64+row)*DIM+c4);
        __half2 h01=__floats2half2_rn(t.x,t.y), h23=__floats2half2_rn(t.z,t.w);
        uint32_t xo=2*SWZH(row,c4);
        *(uint32_t*)((char*)sm+xo)=*(uint32_t*)&h01; *(uint32_t*)((char*)sm+xo+4)=*(uint32_t*)&h23;
    }
#pragma unroll
    for(int i=0;i<16;i++){
        int idx=tid+i*256, row=idx>>5, c4=(idx&31)*4;
        float4 t=*(const float4*)(W+(size_t)row*(8*DIM)+bx*128+c4);
        __half2 h01=__floats2half2_rn(t.x,t.y), h23=__floats2half2_rn(t.z,t.w);
        uint32_t wo=2*SWZH(row,c4);
        *(uint32_t*)((char*)sm+16384+wo)=*(uint32_t*)&h01; *(uint32_t*)((char*)sm+16384+wo+4)=*(uint32_t*)&h23;
    }
    __syncthreads();

    float acc[8][4];
#pragma unroll
    for(int j=0;j<8;j++)
#pragma unroll
        for(int p2=0;p2<4;p2++) acc[j][p2]=0.f;

#pragma unroll
    for(int kc=0;kc<8;kc++){
        uint32_t ah[4];
        ldm4(ah, sb+2*(SWZH(wm*16+lr, kc*16+ldd)));
#pragma unroll
        for(int np=0;np<4;np++){
            uint32_t wh[4];
            ldm4t(wh, sb+2*(8192+SWZH(kc*16+lr, wn*64+np*16+ldd)));
            mmaf(acc[2*np],ah,wh[0],wh[1]); mmaf(acc[2*np+1],ah,wh[2],wh[3]);
        }
    }

    const int g=bm*8+bx;
    const int rbase=by*64+wm*16+(lane>>2);
    const int dbase=wn*64+2*(lane&3);
#pragma unroll
    for(int j=0;j<8;j++)
#pragma unroll
        for(int hr=0;hr<2;hr++){
            int r=rbase+hr*8, d=dbase+j*8;
            size_t off=((size_t)(g*SEQ)+r)*DIM+d;
            *(__half2*)(g_vh0+off)=__floats2half2_rn(acc[j][2*hr],acc[j][2*hr+1]);
        }
}

// ================= Kernel 2: flash attention, Br=64, 128 thr, 2 CTAs/SM =====
// smem halves: buffer b at b*24576: Kh 0 | Kl 8192 | Vh 16384.  96 KB total.
// Q (Qh 0..8192 | Ql 8192..16384) staged inside buf0, consumed before kv0 lands.
#define ATTN_SMEM 98304

__device__ __forceinline__ void load_kv(uint32_t sb, size_t gbase, int t, int buf, int tid){
#pragma unroll
    for(int i=0;i<24;i++){
        int idx=tid+i*128, arr=idx>>10, rem=idx&1023, row=rem>>4, ch=rem&15;
        const __half* src;
        if(arr==0) src=g_kh0; else if(arr==1) src=g_kh1; else src=g_vh0;
        src += gbase+(size_t)(t*64+row)*DIM+ch*8;
        uint32_t dst=sb+2*(buf*24576+arr*8192+SWZH(row,ch*8));
        cpa16(dst,src);
    }
}

__global__ void __launch_bounds__(128,2) attn_kernel()
{
    extern __shared__ __half sm[];
    const uint32_t sb=s2u(sm);
    const int tid=threadIdx.x, warp=tid>>5, lane=tid&31;
    const int g=blockIdx.y, qt=blockIdx.x;     // qt: 0..15 (64-row q tiles)
    const size_t gbase=(size_t)g*SEQ*DIM;
    const int lr=(lane&7)+((lane>>3)&1)*8;
    const int ldd=((lane>>4)&1)*8;

    // stage Q (hi+lo) into buf0 region
#pragma unroll
    for(int i=0;i<16;i++){
        int idx=tid+i*128, arr=idx>>10, rem=idx&1023, row=rem>>4, ch=rem&15;
        const __half* src=(arr? g_qh1:g_qh0)+gbase+(size_t)(qt*64+row)*DIM+ch*8;
        cpa16(sb+2*((arr?8192:0)+SWZH(row,ch*8)), src);
    }
    CPCOMMIT(); CPWAIT0();
    __syncthreads();
    uint32_t qah[8][4], qal[8][4];
#pragma unroll
    for(int kc=0;kc<8;kc++){
        ldm4(qah[kc], sb+2*(SWZH(warp*16+lr, kc*16+ldd)));
        ldm4(qal[kc], sb+2*(8192+SWZH(warp*16+lr, kc*16+ldd)));
    }
    __syncthreads();   // all warps done with smem Q before kv0 overwrites it

    load_kv(sb,gbase,0,0,tid); CPCOMMIT();
    load_kv(sb,gbase,1,1,tid); CPCOMMIT();

    float o[16][4];
#pragma unroll
    for(int i=0;i<16;i++)
#pragma unroll
        for(int j2=0;j2<4;j2++) o[i][j2]=0.f;
    float mA=-1e30f, mB=-1e30f, lA=0.f, lB=0.f;

    for(int t=0;t<16;t++){
        if(t<15) CPWAIT1(); else CPWAIT0();
        __syncthreads();
        const uint32_t KHB=(t&1)*24576, KLB=KHB+8192, VHB=KHB+16384;

        float c[8][4];
#pragma unroll
        for(int j=0;j<8;j++)
#pragma unroll
            for(int i2=0;i2<4;i2++) c[j][i2]=0.f;
#pragma unroll
        for(int kc=0;kc<8;kc++){
#pragma unroll
            for(int np=0;np<4;np++){
                uint32_t kh[4],kl[4];
                ldm4(kh, sb+2*(KHB+SWZH(np*16+lr, kc*16+ldd)));
                ldm4(kl, sb+2*(KLB+SWZH(np*16+lr, kc*16+ldd)));
                mmaf(c[2*np],qah[kc],kh[0],kh[2]); mmaf(c[2*np+1],qah[kc],kh[1],kh[3]);
                mmaf(c[2*np],qah[kc],kl[0],kl[2]); mmaf(c[2*np+1],qah[kc],kl[1],kl[3]);
                mmaf(c[2*np],qal[kc],kh[0],kh[2]); mmaf(c[2*np+1],qal[kc],kh[1],kh[3]);
            }
        }

        float tA=-1e30f, tB=-1e30f;
#pragma unroll
        for(int j=0;j<8;j++){
            tA=fmaxf(tA,fmaxf(c[j][0],c[j][1]));
            tB=fmaxf(tB,fmaxf(c[j][2],c[j][3]));
        }
        tA=fmaxf(tA,__shfl_xor_sync(0xffffffffu,tA,1));
        tA=fmaxf(tA,__shfl_xor_sync(0xffffffffu,tA,2));
        tB=fmaxf(tB,__shfl_xor_sync(0xffffffffu,tB,1));
        tB=fmaxf(tB,__shfl_xor_sync(0xffffffffu,tB,2));
        float mnA=fmaxf(mA,tA), mnB=fmaxf(mB,tB);
        float cA=fex2(mA-mnA), cB=fex2(mB-mnB);
        mA=mnA; mB=mnB;
        uint32_t pa[8], pb[8];
        float sA=0.f, sB=0.f;
#pragma unroll
        for(int j=0;j<8;j++){
            float p0=fex2(c[j][0]-mnA), p1=fex2(c[j][1]-mnA);
            float p2=fex2(c[j][2]-mnB), p3=fex2(c[j][3]-mnB);
            sA+=p0+p1; sB+=p2+p3;
            pa[j]=pkh(p0,p1); pb[j]=pkh(p2,p3);
        }
        lA=lA*cA+sA; lB=lB*cB+sB;
        if(cA!=1.f){
#pragma unroll
            for(int dt=0;dt<16;dt++){ o[dt][0]*=cA; o[dt][1]*=cA; }
        }
        if(cB!=1.f){
#pragma unroll
            for(int dt=0;dt<16;dt++){ o[dt][2]*=cB; o[dt][3]*=cB; }
        }

#pragma unroll
        for(int kc=0;kc<4;kc++){
            uint32_t a4[4]={pa[2*kc],pb[2*kc],pa[2*kc+1],pb[2*kc+1]};
#pragma unroll
            for(int dp=0;dp<8;dp++){
                uint32_t vh[4];
                ldm4t(vh, sb+2*(VHB+SWZH(kc*16+lr, dp*16+ldd)));
                mmaf(o[2*dp],a4,vh[0],vh[1]); mmaf(o[2*dp+1],a4,vh[2],vh[3]);
            }
        }
        __syncthreads();
        if(t+2<16){ load_kv(sb,gbase,t+2,t&1,tid); CPCOMMIT(); }
    }

    lA+=__shfl_xor_sync(0xffffffffu,lA,1); lA+=__shfl_xor_sync(0xffffffffu,lA,2);
    lB+=__shfl_xor_sync(0xffffffffu,lB,1); lB+=__shfl_xor_sync(0xffffffffu,lB,2);
    float iA=1.f/lA, iB=1.f/lB;
    int rA=qt*64+warp*16+(lane>>2), rB=rA+8, dc=2*(lane&3);
    __half* obase=g_oh+gbase;
#pragma unroll
    for(int dt=0;dt<16;dt++){
        *(__half2*)(obase+(size_t)rA*DIM+dt*8+dc)=__floats2half2_rn(o[dt][0]*iA,o[dt][1]*iA);
        *(__half2*)(obase+(size_t)rB*DIM+dt*8+dc)=__floats2half2_rn(o[dt][2]*iB,o[dt][3]*iB);
    }
}

// ================= Kernel 3: head-mean + residual (fp16 g_oh) ===============
__global__ void __launch_bounds__(256) reduce_kernel(const float* __restrict__ q, float* __restrict__ out)
{
    int i4=blockIdx.x*256+threadIdx.x;     // float4 index, 262144 total
    int bm=i4>>15, r4=i4&32767;
    float sx=0,sy=0,sz=0,sw=0;
#pragma unroll
    for(int h=0;h<8;h++){
        uint2 v=*(const uint2*)(g_oh+((size_t)(bm*8+h))*131072+(size_t)r4*4);
        __half2 a=*(__half2*)&v.x, b=*(__half2*)&v.y;
        float2 fa=__half22float2(a), fb=__half22float2(b);
        sx+=fa.x; sy+=fa.y; sz+=fb.x; sw+=fb.y;
    }
    float4 qv=((const float4*)q)[i4];
    ((float4*)out)[i4]=make_float4(qv.x+0.125f*sx,qv.y+0.125f*sy,qv.z+0.125f*sz,qv.w+0.125f*sw);
}

extern "C" void kernel_launch(void* const* d_in, const int* in_sizes, int n_in,
                              void* d_out, int out_size)
{
    const float *q=(const float*)d_in[0], *k=(const float*)d_in[1], *v=(const float*)d_in[2];
    const float *Wq=(const float*)d_in[3], *Wk=(const float*)d_in[4], *Wv=(const float*)d_in[5];
    float* out=(float*)d_out;
    cudaFuncSetAttribute(proj_qk_kernel, cudaFuncAttributeMaxDynamicSharedMemorySize, PROJQK_SMEM);
    cudaFuncSetAttribute(proj_v_kernel, cudaFuncAttributeMaxDynamicSharedMemorySize, PROJV_SMEM);
    cudaFuncSetAttribute(attn_kernel, cudaFuncAttributeMaxDynamicSharedMemorySize, ATTN_SMEM);
    proj_qk_kernel<<<dim3(8,16,16),256,PROJQK_SMEM>>>(q,k,Wq,Wk);
    proj_v_kernel <<<dim3(8,16,8),256,PROJV_SMEM>>>(v,Wv);
    attn_kernel<<<dim3(16,64),128,ATTN_SMEM>>>();
    reduce_kernel<<<1024,256>>>(q,out);
}